// round 1
// baseline (speedup 1.0000x reference)
#include <cuda_runtime.h>
#include <cuda_bf16.h>
#include <math.h>

// Problem constants
#define BB 2
#define SS 2048
#define DD 2048
#define HH 16
#define DHH 128
#define FF 5632
#define MM (BB * SS)   // 4096 rows flattened

// ---------------- scratch (device globals; no allocation allowed) ----------
__device__ float g_x   [(long long)MM * DD];
__device__ float g_q   [(long long)MM * DD];
__device__ float g_k   [(long long)MM * DD];
__device__ float g_v   [(long long)MM * DD];
__device__ float g_sc  [(long long)BB * HH * SS * SS];   // 536 MB scores
__device__ float g_attn[(long long)MM * DD];
__device__ float g_h   [(long long)MM * DD];
__device__ float g_y   [(long long)MM * DD];
__device__ float g_f1  [(long long)MM * FF];
__device__ float g_f3  [(long long)MM * FF];

// ---------------- generic strided/batched SGEMM ----------------------------
// C[m][n] = alpha * sum_k A[m*lda + k] * B[k*ldbk + n*ldbn] (+ Res[m*ldres+n])
// batch index z -> (bb = z / batchH, hh = z % batchH), pointer offsets via strides.
#define BM 128
#define BN 128
#define BK 16
#define TM 8
#define TN 8

__global__ __launch_bounds__(256)
void sgemm_kernel(const float* __restrict__ A, const float* __restrict__ B,
                  const float* __restrict__ Res, float* __restrict__ C,
                  int M, int N, int K,
                  int lda, int ldbk, int ldbn, int ldc, int ldres,
                  int batchH,
                  long long sAb, long long sAh, long long sBb, long long sBh,
                  long long sCb, long long sCh, long long sRb, long long sRh,
                  float alpha)
{
    __shared__ float As[BK][BM + 1];
    __shared__ float Bs[BK][BN];

    int z  = blockIdx.z;
    int bb = z / batchH;
    int hh = z - bb * batchH;
    A += bb * sAb + hh * sAh;
    B += bb * sBb + hh * sBh;
    C += bb * sCb + hh * sCh;
    if (Res) Res += bb * sRb + hh * sRh;

    const int m0 = blockIdx.y * BM;
    const int n0 = blockIdx.x * BN;
    const int tid = threadIdx.x;
    const int tx = tid & 15;       // 0..15
    const int ty = tid >> 4;       // 0..15

    float acc[TM][TN];
#pragma unroll
    for (int i = 0; i < TM; i++)
#pragma unroll
        for (int j = 0; j < TN; j++) acc[i][j] = 0.0f;

    for (int k0 = 0; k0 < K; k0 += BK) {
        // load A tile: BM x BK = 2048 elems, 8 per thread
#pragma unroll
        for (int t = 0; t < 8; t++) {
            int idx = tid + t * 256;
            int r = idx >> 4;      // /BK
            int c = idx & 15;      // %BK
            As[c][r] = A[(long long)(m0 + r) * lda + (k0 + c)];
        }
        // load B tile: BK x BN = 2048 elems
#pragma unroll
        for (int t = 0; t < 8; t++) {
            int idx = tid + t * 256;
            int r = idx >> 7;      // /BN
            int c = idx & 127;     // %BN
            Bs[r][c] = B[(long long)(k0 + r) * ldbk + (long long)(n0 + c) * ldbn];
        }
        __syncthreads();

#pragma unroll
        for (int k = 0; k < BK; k++) {
            float ar[TM], br[TN];
#pragma unroll
            for (int i = 0; i < TM; i++) ar[i] = As[k][ty * TM + i];
#pragma unroll
            for (int j = 0; j < TN; j++) br[j] = Bs[k][tx * TN + j];
#pragma unroll
            for (int i = 0; i < TM; i++)
#pragma unroll
                for (int j = 0; j < TN; j++)
                    acc[i][j] = fmaf(ar[i], br[j], acc[i][j]);
        }
        __syncthreads();
    }

#pragma unroll
    for (int i = 0; i < TM; i++) {
        int m = m0 + ty * TM + i;
#pragma unroll
        for (int j = 0; j < TN; j++) {
            int n = n0 + tx * TN + j;
            float v = alpha * acc[i][j];
            if (Res) v += Res[(long long)m * ldres + n];
            C[(long long)m * ldc + n] = v;
        }
    }
}

// ---------------- RMSNorm ---------------------------------------------------
__global__ __launch_bounds__(256)
void rmsnorm_kernel(const float* __restrict__ in, const float* __restrict__ w,
                    float* __restrict__ out, int D)
{
    __shared__ float red[256];
    const long long row = blockIdx.x;
    const float* p = in + row * D;
    float* o = out + row * D;
    int tid = threadIdx.x;

    float ss = 0.0f;
    for (int j = tid; j < D; j += 256) {
        float v = p[j];
        ss += v * v;
    }
    red[tid] = ss;
    __syncthreads();
    for (int s = 128; s > 0; s >>= 1) {
        if (tid < s) red[tid] += red[tid + s];
        __syncthreads();
    }
    float scale = rsqrtf(red[0] / (float)D + 1e-6f);
    for (int j = tid; j < D; j += 256)
        o[j] = p[j] * scale * w[j];
}

// ---------------- RoPE (in-place on q and k) --------------------------------
__global__ __launch_bounds__(256)
void rope_kernel(float* __restrict__ q, float* __restrict__ k,
                 const float* __restrict__ fcos, const float* __restrict__ fsin)
{
    long long idx = (long long)blockIdx.x * 256 + threadIdx.x; // over B*S*H*(DH/2)
    const int HALF = DHH / 2;   // 64
    int i = idx & (HALF - 1);
    long long t = idx >> 6;     // /64
    int h = t & (HH - 1);
    t >>= 4;                    // /16
    int s = t & (SS - 1);
    long long bs = t >> 11;     // /2048 -> b
    long long base = (((bs * SS + s) * HH + h) * DHH) + 2 * i;

    float c  = fcos[(long long)s * HALF + i];
    float sn = fsin[(long long)s * HALF + i];

    float xr = q[base], xi = q[base + 1];
    q[base]     = xr * c - xi * sn;
    q[base + 1] = xr * sn + xi * c;

    xr = k[base]; xi = k[base + 1];
    k[base]     = xr * c - xi * sn;
    k[base + 1] = xr * sn + xi * c;
}

// ---------------- causal softmax (in-place on scores) -----------------------
__global__ __launch_bounds__(256)
void softmax_causal_kernel(float* __restrict__ scores)
{
    __shared__ float red[256];
    const int row = blockIdx.x;     // query position
    const int bh  = blockIdx.y;     // b*H + h
    float* p = scores + ((long long)bh * SS + row) * (long long)SS;
    const int n = row + 1;          // valid keys
    int tid = threadIdx.x;

    float mx = -3.402823e38f;
    for (int j = tid; j < n; j += 256) mx = fmaxf(mx, p[j]);
    red[tid] = mx;
    __syncthreads();
    for (int s = 128; s > 0; s >>= 1) {
        if (tid < s) red[tid] = fmaxf(red[tid], red[tid + s]);
        __syncthreads();
    }
    mx = red[0];
    __syncthreads();

    float sum = 0.0f;
    for (int j = tid; j < n; j += 256) {
        float e = __expf(p[j] - mx);
        p[j] = e;
        sum += e;
    }
    red[tid] = sum;
    __syncthreads();
    for (int s = 128; s > 0; s >>= 1) {
        if (tid < s) red[tid] += red[tid + s];
        __syncthreads();
    }
    float inv = 1.0f / red[0];

    for (int j = tid; j < n; j += 256) p[j] *= inv;
    for (int j = n + tid; j < SS; j += 256) p[j] = 0.0f;   // zero masked tail
}

// ---------------- SiLU-mul ---------------------------------------------------
__global__ __launch_bounds__(256)
void silu_mul_kernel(float* __restrict__ g1, const float* __restrict__ g3)
{
    long long i = (long long)blockIdx.x * 256 + threadIdx.x;
    float a = g1[i];
    float s = a / (1.0f + __expf(-a));
    g1[i] = s * g3[i];
}

// ---------------- host-side helpers -----------------------------------------
static void gemm(const float* A, const float* Bm, const float* Res, float* C,
                 int M, int N, int K,
                 int lda, int ldbk, int ldbn, int ldc, int ldres,
                 int nbatch, int batchH,
                 long long sAb, long long sAh, long long sBb, long long sBh,
                 long long sCb, long long sCh, long long sRb, long long sRh,
                 float alpha)
{
    dim3 grid(N / BN, M / BM, nbatch);
    sgemm_kernel<<<grid, 256>>>(A, Bm, Res, C, M, N, K,
                                lda, ldbk, ldbn, ldc, ldres, batchH,
                                sAb, sAh, sBb, sBh, sCb, sCh, sRb, sRh, alpha);
}

extern "C" void kernel_launch(void* const* d_in, const int* in_sizes, int n_in,
                              void* d_out, int out_size)
{
    (void)in_sizes; (void)n_in; (void)out_size;
    const float* hidden = (const float*)d_in[0];
    const float* fcos   = (const float*)d_in[1];
    const float* fsin   = (const float*)d_in[2];
    const float* wq     = (const float*)d_in[3];
    const float* wk     = (const float*)d_in[4];
    const float* wv     = (const float*)d_in[5];
    const float* wo     = (const float*)d_in[6];
    const float* w1     = (const float*)d_in[7];
    const float* w2     = (const float*)d_in[8];
    const float* w3     = (const float*)d_in[9];
    const float* anw    = (const float*)d_in[10];
    const float* fnw    = (const float*)d_in[11];
    float* out = (float*)d_out;

    float *x, *q, *k, *v, *sc, *attn, *h, *y, *f1, *f3;
    cudaGetSymbolAddress((void**)&x,    g_x);
    cudaGetSymbolAddress((void**)&q,    g_q);
    cudaGetSymbolAddress((void**)&k,    g_k);
    cudaGetSymbolAddress((void**)&v,    g_v);
    cudaGetSymbolAddress((void**)&sc,   g_sc);
    cudaGetSymbolAddress((void**)&attn, g_attn);
    cudaGetSymbolAddress((void**)&h,    g_h);
    cudaGetSymbolAddress((void**)&y,    g_y);
    cudaGetSymbolAddress((void**)&f1,   g_f1);
    cudaGetSymbolAddress((void**)&f3,   g_f3);

    const long long SH  = (long long)SS * DD;       // per-batch stride of [B,S,H*DH]
    const long long SSS = (long long)SS * SS;       // per-head stride of scores
    const float scale = 0.08838834764831845f;       // 1/sqrt(128)

    // 1. x = rmsnorm(hidden, attn_norm_w)
    rmsnorm_kernel<<<MM, 256>>>(hidden, anw, x, DD);

    // 2. q/k/v = x @ wq/wk/wv   (4096 x 2048 x 2048)
    gemm(x, wq, nullptr, q, MM, DD, DD, DD, DD, 1, DD, 0, 1, 1, 0,0,0,0,0,0,0,0, 1.0f);
    gemm(x, wk, nullptr, k, MM, DD, DD, DD, DD, 1, DD, 0, 1, 1, 0,0,0,0,0,0,0,0, 1.0f);
    gemm(x, wv, nullptr, v, MM, DD, DD, DD, DD, 1, DD, 0, 1, 1, 0,0,0,0,0,0,0,0, 1.0f);

    // 3. RoPE on q and k (in place)
    {
        long long npairs = (long long)BB * SS * HH * (DHH / 2); // 4,194,304
        rope_kernel<<<(unsigned)(npairs / 256), 256>>>(q, k, fcos, fsin);
    }

    // 4. scores[b,h,i,j] = scale * q_i . k_j   (batched over 32 (b,h))
    gemm(q, k, nullptr, sc, SS, SS, DHH,
         DD,        /*lda: q row stride*/
         1, DD,     /*B: k as K^T -> B[k=d][n=j] = k[j*2048 + d]*/
         SS, 0,
         BB * HH, HH,
         SH, DHH,   /*A strides per b,h*/
         SH, DHH,   /*B strides per b,h*/
         (long long)HH * SSS, SSS,  /*C strides*/
         0, 0, scale);

    // 5. causal softmax in place
    {
        dim3 g(SS, BB * HH);
        softmax_causal_kernel<<<g, 256>>>(sc);
    }

    // 6. attn = probs @ v   (batched, M=2048, N=128, K=2048)
    gemm(sc, v, nullptr, attn, SS, DHH, SS,
         SS,         /*lda*/
         DD, 1,      /*B: v[j*2048 + d]*/
         DD, 0,      /*ldc: attn row stride H*DH*/
         BB * HH, HH,
         (long long)HH * SSS, SSS,
         SH, DHH,
         SH, DHH,
         0, 0, 1.0f);

    // 7. h = hidden + attn @ wo
    gemm(attn, wo, hidden, h, MM, DD, DD, DD, DD, 1, DD, DD, 1, 1,
         0,0,0,0,0,0,0,0, 1.0f);

    // 8. y = rmsnorm(h, ffn_norm_w)
    rmsnorm_kernel<<<MM, 256>>>(h, fnw, y, DD);

    // 9. f1 = y @ w1 ; f3 = y @ w3    (4096 x 5632 x 2048)
    gemm(y, w1, nullptr, f1, MM, FF, DD, DD, FF, 1, FF, 0, 1, 1,
         0,0,0,0,0,0,0,0, 1.0f);
    gemm(y, w3, nullptr, f3, MM, FF, DD, DD, FF, 1, FF, 0, 1, 1,
         0,0,0,0,0,0,0,0, 1.0f);

    // 10. f1 = silu(f1) * f3
    {
        long long n = (long long)MM * FF; // 23,068,672
        silu_mul_kernel<<<(unsigned)(n / 256), 256>>>(f1, f3);
    }

    // 11. out = h + f1 @ w2    (4096 x 2048 x 5632)
    gemm(f1, w2, h, out, MM, DD, FF, FF, DD, 1, DD, DD, 1, 1,
         0,0,0,0,0,0,0,0, 1.0f);
}

// round 3
// speedup vs baseline: 3.0245x; 3.0245x over previous
#include <cuda_runtime.h>
#include <cuda_fp16.h>
#include <math.h>
#include <stdint.h>

#define BBATCH 2
#define SS 2048
#define DD 2048
#define HH 16
#define DHH 128
#define FFD 5632
#define MM (BBATCH * SS)

typedef __half h16;

// ------------------------- scratch (device globals) -------------------------
__device__ h16   g_xb  [(long long)MM * DD];
__device__ h16   g_wqT [(long long)DD * DD];
__device__ h16   g_wkT [(long long)DD * DD];
__device__ h16   g_wvT [(long long)DD * DD];
__device__ h16   g_woT [(long long)DD * DD];
__device__ h16   g_w1Th[(long long)FFD * DD];
__device__ h16   g_w1Tl[(long long)FFD * DD];
__device__ h16   g_w3Th[(long long)FFD * DD];
__device__ h16   g_w3Tl[(long long)FFD * DD];
__device__ h16   g_w2Th[(long long)DD * FFD];
__device__ h16   g_w2Tl[(long long)DD * FFD];
__device__ float g_q   [(long long)MM * DD];
__device__ float g_k   [(long long)MM * DD];
__device__ float g_v   [(long long)MM * DD];
__device__ h16   g_qb  [(long long)MM * DD];
__device__ h16   g_kb  [(long long)MM * DD];
__device__ h16   g_vt  [(long long)BBATCH * HH * DHH * SS];
__device__ float g_sc  [(long long)BBATCH * HH * SS * SS];
__device__ h16   g_pb  [(long long)BBATCH * HH * SS * SS];
__device__ float g_attn[(long long)MM * DD];
__device__ h16   g_attnb[(long long)MM * DD];
__device__ float g_h   [(long long)MM * DD];
__device__ h16   g_yh  [(long long)MM * DD];
__device__ h16   g_yl  [(long long)MM * DD];
__device__ float g_f1  [(long long)MM * FFD];
__device__ float g_f3  [(long long)MM * FFD];
__device__ h16   g_gh  [(long long)MM * FFD];
__device__ h16   g_gl  [(long long)MM * FFD];

// ------------------------- helpers ------------------------------------------
__device__ __forceinline__ uint32_t smem_u32(const void* p) {
    uint32_t a;
    asm("{ .reg .u64 t; cvta.to.shared.u64 t, %1; cvt.u32.u64 %0, t; }" : "=r"(a) : "l"(p));
    return a;
}

__device__ __forceinline__ void cp_async16(uint32_t dst, const void* src) {
    asm volatile("cp.async.cg.shared.global [%0], [%1], 16;" :: "r"(dst), "l"(src));
}
__device__ __forceinline__ void cp_commit() {
    asm volatile("cp.async.commit_group;");
}
__device__ __forceinline__ void cp_wait1() {
    asm volatile("cp.async.wait_group 1;");
}

__device__ __forceinline__ void ldmx4(uint32_t* r, uint32_t addr) {
    asm volatile("ldmatrix.sync.aligned.m8n8.x4.shared.b16 {%0,%1,%2,%3}, [%4];"
                 : "=r"(r[0]), "=r"(r[1]), "=r"(r[2]), "=r"(r[3]) : "r"(addr));
}
__device__ __forceinline__ void ldmx2(uint32_t* r, uint32_t addr) {
    asm volatile("ldmatrix.sync.aligned.m8n8.x2.shared.b16 {%0,%1}, [%2];"
                 : "=r"(r[0]), "=r"(r[1]) : "r"(addr));
}
__device__ __forceinline__ void mma16816(float* c, const uint32_t* a, const uint32_t* b) {
    asm volatile(
        "mma.sync.aligned.m16n8k16.row.col.f32.f16.f16.f32 "
        "{%0,%1,%2,%3}, {%4,%5,%6,%7}, {%8,%9}, {%0,%1,%2,%3};"
        : "+f"(c[0]), "+f"(c[1]), "+f"(c[2]), "+f"(c[3])
        : "r"(a[0]), "r"(a[1]), "r"(a[2]), "r"(a[3]), "r"(b[0]), "r"(b[1]));
}

// ------------------------- HGEMM (mma.sync) ----------------------------------
// C[m][n] = alpha * sum_k A[m][k]*B[n][k] (+Res). A: [M,lda] K-major fp16,
// B: [N,ldb] K-major fp16. passes==3: hi*hi + hi*lo + lo*hi split.
// CTA tile 128x128, BK=64, 3-stage cp.async pipeline, 8 warps (2m x 4n).

// stage layout (bytes): Ah @0 (16K), [Al @16K], Bh @bOff (16K), [Bl @bOff+16K]
__device__ __forceinline__ void stage_load(uint32_t sdst, const h16* g, int row0,
                                           long long ld, int k0, int tid)
{
    const int r = tid >> 1;                 // 0..127
    const int cb = (tid & 1) * 4;           // chunk base
    const h16* grow = g + (long long)(row0 + r) * ld + k0;
#pragma unroll
    for (int i = 0; i < 4; i++) {
        int c = cb + i;
        uint32_t dst = sdst + (uint32_t)(r * 128 + ((c ^ (r & 7)) * 16));
        cp_async16(dst, grow + c * 8);
    }
}

__global__ __launch_bounds__(256, 1)
void hgemm(const h16* __restrict__ Ahi, const h16* __restrict__ Alo,
           const h16* __restrict__ Bhi, const h16* __restrict__ Blo,
           const float* __restrict__ Res, float* __restrict__ C,
           int M, int N, int K,
           long long lda, long long ldb, long long ldc, long long ldres,
           int batchH,
           long long sAb, long long sAh, long long sBb, long long sBh,
           long long sCb, long long sCh, long long sRb, long long sRh,
           float alpha, int passes, int causal)
{
    extern __shared__ char smem[];

    const int m0 = blockIdx.y * 128;
    const int n0 = blockIdx.x * 128;
    if (causal == 1 && n0 > m0 + 127) return;
    int kEnd = K;
    if (causal == 2) kEnd = min(K, m0 + 128);

    const int z = blockIdx.z;
    const int bb = z / batchH;
    const int hh = z - bb * batchH;
    Ahi += bb * sAb + hh * sAh;
    if (Alo) Alo += bb * sAb + hh * sAh;
    Bhi += bb * sBb + hh * sBh;
    if (Blo) Blo += bb * sBb + hh * sBh;
    C += bb * sCb + hh * sCh;
    if (Res) Res += bb * sRb + hh * sRh;

    const int tid = threadIdx.x;
    const int lane = tid & 31;
    const int wid = tid >> 5;
    const int wm = wid >> 2;          // 0..1
    const int wn = wid & 3;           // 0..3

    const uint32_t stageBytes = (passes == 3) ? 65536u : 32768u;
    const uint32_t bOff = (passes == 3) ? 32768u : 16384u;
    const uint32_t sb = smem_u32(smem);

    const int KT = kEnd >> 6;         // 64-wide k stages

    // ---- prologue: prefetch up to 2 stages
    const int nPro = (KT < 2) ? KT : 2;
    for (int s = 0; s < nPro; s++) {
        uint32_t base = sb + (uint32_t)(s % 3) * stageBytes;
        stage_load(base, Ahi, m0, lda, s * 64, tid);
        stage_load(base + bOff, Bhi, n0, ldb, s * 64, tid);
        if (passes == 3) {
            stage_load(base + 16384u, Alo, m0, lda, s * 64, tid);
            stage_load(base + bOff + 16384u, Blo, n0, ldb, s * 64, tid);
        }
        cp_commit();
    }

    float acc[4][4][4];
#pragma unroll
    for (int i = 0; i < 4; i++)
#pragma unroll
        for (int j = 0; j < 4; j++)
#pragma unroll
            for (int q = 0; q < 4; q++) acc[i][j][q] = 0.0f;

    // lane-fixed address pieces
    const int aRow = wm * 64 + (lane & 15);           // + mt*16
    const int aKsel = lane >> 4;                      // 0/1 (k chunk half)
    const int aSwz = aRow & 7;
    const int bRowBase = wn * 32 + (lane & 7);        // + nt*8
    const int bKsel = (lane >> 3) & 1;

    for (int s = 0; s < KT; s++) {
        cp_wait1();
        __syncthreads();
        if (s + 2 < KT) {
            uint32_t base = sb + (uint32_t)((s + 2) % 3) * stageBytes;
            stage_load(base, Ahi, m0, lda, (s + 2) * 64, tid);
            stage_load(base + bOff, Bhi, n0, ldb, (s + 2) * 64, tid);
            if (passes == 3) {
                stage_load(base + 16384u, Alo, m0, lda, (s + 2) * 64, tid);
                stage_load(base + bOff + 16384u, Blo, n0, ldb, (s + 2) * 64, tid);
            }
        }
        cp_commit();

        const uint32_t base = sb + (uint32_t)(s % 3) * stageBytes;
#pragma unroll
        for (int kc = 0; kc < 4; kc++) {
            uint32_t a[4][4], b[4][2];
            uint32_t al[4][4], bl[4][2];
#pragma unroll
            for (int mt = 0; mt < 4; mt++) {
                uint32_t ad = base + (uint32_t)((aRow + mt * 16) * 128 +
                              (((kc * 2 + aKsel) ^ aSwz) * 16));
                ldmx4(a[mt], ad);
                if (passes == 3) ldmx4(al[mt], ad + 16384u);
            }
#pragma unroll
            for (int nt = 0; nt < 4; nt++) {
                int nRow = bRowBase + nt * 8;
                uint32_t bd = base + bOff + (uint32_t)(nRow * 128 +
                              (((kc * 2 + bKsel) ^ (nRow & 7)) * 16));
                ldmx2(b[nt], bd);
                if (passes == 3) ldmx2(bl[nt], bd + 16384u);
            }
#pragma unroll
            for (int mt = 0; mt < 4; mt++)
#pragma unroll
                for (int nt = 0; nt < 4; nt++) {
                    mma16816(acc[mt][nt], a[mt], b[nt]);
                    if (passes == 3) {
                        mma16816(acc[mt][nt], a[mt], bl[nt]);
                        mma16816(acc[mt][nt], al[mt], b[nt]);
                    }
                }
        }
        __syncthreads();
    }

    // ---- epilogue: registers -> C (fp32), with alpha and optional residual
#pragma unroll
    for (int mt = 0; mt < 4; mt++) {
#pragma unroll
        for (int nt = 0; nt < 4; nt++) {
            const int m = m0 + wm * 64 + mt * 16 + (lane >> 2);
            const int n = n0 + wn * 32 + nt * 8 + (lane & 3) * 2;
            float2 v0, v1;
            v0.x = acc[mt][nt][0] * alpha; v0.y = acc[mt][nt][1] * alpha;
            v1.x = acc[mt][nt][2] * alpha; v1.y = acc[mt][nt][3] * alpha;
            if (Res) {
                float2 r0 = *reinterpret_cast<const float2*>(&Res[(long long)m * ldres + n]);
                float2 r1 = *reinterpret_cast<const float2*>(&Res[(long long)(m + 8) * ldres + n]);
                v0.x += r0.x; v0.y += r0.y; v1.x += r1.x; v1.y += r1.y;
            }
            *reinterpret_cast<float2*>(&C[(long long)m * ldc + n]) = v0;
            *reinterpret_cast<float2*>(&C[(long long)(m + 8) * ldc + n]) = v1;
        }
    }
}

// ------------------------- elementwise kernels --------------------------------
__global__ __launch_bounds__(256)
void rmsnorm_split(const float* __restrict__ in, const float* __restrict__ w,
                   h16* __restrict__ hi, h16* __restrict__ lo)
{
    __shared__ float red[256];
    const long long row = blockIdx.x;
    const float* p = in + row * DD;
    const int tid = threadIdx.x;
    float v[8];
    float ss = 0.0f;
#pragma unroll
    for (int t = 0; t < 8; t++) { v[t] = p[tid + t * 256]; ss += v[t] * v[t]; }
    red[tid] = ss;
    __syncthreads();
    for (int s = 128; s > 0; s >>= 1) {
        if (tid < s) red[tid] += red[tid + s];
        __syncthreads();
    }
    const float scale = rsqrtf(red[0] / (float)DD + 1e-6f);
#pragma unroll
    for (int t = 0; t < 8; t++) {
        int j = tid + t * 256;
        float o = v[t] * scale * w[j];
        h16 h = __float2half_rn(o);
        hi[row * DD + j] = h;
        if (lo) lo[row * DD + j] = __float2half_rn(o - __half2float(h));
    }
}

// W [K,N] fp32 -> WT [N,K] fp16 (hi/lo)
__global__ __launch_bounds__(256)
void transpose_split(const float* __restrict__ W, h16* __restrict__ hi,
                     h16* __restrict__ lo, int K, int N)
{
    __shared__ float t[32][33];
    const int k0 = blockIdx.y * 32, n0 = blockIdx.x * 32;
    const int tx = threadIdx.x & 31, ty = threadIdx.x >> 5;
#pragma unroll
    for (int i = 0; i < 32; i += 8)
        t[ty + i][tx] = W[(long long)(k0 + ty + i) * N + n0 + tx];
    __syncthreads();
#pragma unroll
    for (int i = 0; i < 32; i += 8) {
        float v = t[tx][ty + i];
        long long o = (long long)(n0 + ty + i) * K + k0 + tx;
        h16 h = __float2half_rn(v);
        hi[o] = h;
        if (lo) lo[o] = __float2half_rn(v - __half2float(h));
    }
}

__global__ __launch_bounds__(256)
void rope_h16(const float* __restrict__ q, const float* __restrict__ k,
              const float* __restrict__ fcos, const float* __restrict__ fsin,
              h16* __restrict__ qb, h16* __restrict__ kb)
{
    long long idx = (long long)blockIdx.x * 256 + threadIdx.x;
    const int HALF = DHH / 2;
    int i = idx & (HALF - 1);
    long long t = idx >> 6;
    int h = t & (HH - 1);
    t >>= 4;
    int s = t & (SS - 1);
    long long b = t >> 11;
    long long base = (((b * SS + s) * HH + h) * DHH) + 2 * i;

    float c  = fcos[(long long)s * HALF + i];
    float sn = fsin[(long long)s * HALF + i];

    float xr = q[base], xi = q[base + 1];
    qb[base]     = __float2half_rn(xr * c - xi * sn);
    qb[base + 1] = __float2half_rn(xr * sn + xi * c);
    xr = k[base]; xi = k[base + 1];
    kb[base]     = __float2half_rn(xr * c - xi * sn);
    kb[base + 1] = __float2half_rn(xr * sn + xi * c);
}

// v [B,S,H*DH] fp32 -> vt [B,H,DH,S] fp16
__global__ __launch_bounds__(256)
void v_transpose(const float* __restrict__ v, h16* __restrict__ vt)
{
    __shared__ float t[32][33];
    const int z = blockIdx.z;
    const int b = z >> 4, h = z & 15;
    const float* src = v + (long long)b * SS * DD + h * DHH;
    h16* dst = vt + (long long)z * DHH * SS;
    const int s0 = blockIdx.x * 32, d0 = blockIdx.y * 32;
    const int tx = threadIdx.x & 31, ty = threadIdx.x >> 5;
#pragma unroll
    for (int i = 0; i < 32; i += 8)
        t[ty + i][tx] = src[(long long)(s0 + ty + i) * DD + d0 + tx];
    __syncthreads();
#pragma unroll
    for (int i = 0; i < 32; i += 8)
        dst[(long long)(d0 + ty + i) * SS + s0 + tx] = __float2half_rn(t[tx][ty + i]);
}

__global__ __launch_bounds__(256)
void softmax_h16(const float* __restrict__ sc, h16* __restrict__ pb)
{
    __shared__ float red[256];
    const int row = blockIdx.x;
    const int bh  = blockIdx.y;
    const float* p = sc + ((long long)bh * SS + row) * (long long)SS;
    h16* o = pb + ((long long)bh * SS + row) * (long long)SS;
    const int n = row + 1;
    const int tid = threadIdx.x;

    float v[8];
    float mx = -3.402823e38f;
#pragma unroll
    for (int t = 0; t < 8; t++) {
        int j = tid + t * 256;
        if (j < n) { v[t] = p[j]; mx = fmaxf(mx, v[t]); }
    }
    red[tid] = mx;
    __syncthreads();
    for (int s = 128; s > 0; s >>= 1) {
        if (tid < s) red[tid] = fmaxf(red[tid], red[tid + s]);
        __syncthreads();
    }
    mx = red[0];
    __syncthreads();
    float sum = 0.0f;
#pragma unroll
    for (int t = 0; t < 8; t++) {
        int j = tid + t * 256;
        if (j < n) { v[t] = __expf(v[t] - mx); sum += v[t]; }
    }
    red[tid] = sum;
    __syncthreads();
    for (int s = 128; s > 0; s >>= 1) {
        if (tid < s) red[tid] += red[tid + s];
        __syncthreads();
    }
    const float inv = 1.0f / red[0];
#pragma unroll
    for (int t = 0; t < 8; t++) {
        int j = tid + t * 256;
        o[j] = __float2half_rn((j < n) ? v[t] * inv : 0.0f);
    }
}

__global__ __launch_bounds__(256)
void to_h16(const float* __restrict__ in, h16* __restrict__ hi)
{
    long long i = (long long)blockIdx.x * 256 + threadIdx.x;
    hi[i] = __float2half_rn(in[i]);
}

__global__ __launch_bounds__(256)
void silu_split(const float* __restrict__ f1, const float* __restrict__ f3,
                h16* __restrict__ hi, h16* __restrict__ lo)
{
    long long i = (long long)blockIdx.x * 256 + threadIdx.x;
    float a = f1[i];
    float g = (a / (1.0f + __expf(-a))) * f3[i];
    h16 h = __float2half_rn(g);
    hi[i] = h;
    lo[i] = __float2half_rn(g - __half2float(h));
}

// ------------------------- host ----------------------------------------------
#define GEMM_SMEM_MAX (3 * 65536)

static void gemm(const h16* Ah, const h16* Al, const h16* Bh, const h16* Bl,
                 const float* Res, float* C, int M, int N, int K,
                 long long lda, long long ldb, long long ldc, long long ldres,
                 int nbatch, int batchH,
                 long long sAb, long long sAh, long long sBb, long long sBh,
                 long long sCb, long long sCh, long long sRb, long long sRh,
                 float alpha, int passes, int causal)
{
    dim3 grid(N / 128, M / 128, nbatch);
    size_t smem = (passes == 3) ? (size_t)3 * 65536 : (size_t)3 * 32768;
    hgemm<<<grid, 256, smem>>>(Ah, Al, Bh, Bl, Res, C, M, N, K,
                               lda, ldb, ldc, ldres, batchH,
                               sAb, sAh, sBb, sBh, sCb, sCh, sRb, sRh,
                               alpha, passes, causal);
}

extern "C" void kernel_launch(void* const* d_in, const int* in_sizes, int n_in,
                              void* d_out, int out_size)
{
    (void)in_sizes; (void)n_in; (void)out_size;
    const float* hidden = (const float*)d_in[0];
    const float* fcos   = (const float*)d_in[1];
    const float* fsin   = (const float*)d_in[2];
    const float* wq     = (const float*)d_in[3];
    const float* wk     = (const float*)d_in[4];
    const float* wv     = (const float*)d_in[5];
    const float* wo     = (const float*)d_in[6];
    const float* w1     = (const float*)d_in[7];
    const float* w2     = (const float*)d_in[8];
    const float* w3     = (const float*)d_in[9];
    const float* anw    = (const float*)d_in[10];
    const float* fnw    = (const float*)d_in[11];
    float* out = (float*)d_out;

    cudaFuncSetAttribute(hgemm, cudaFuncAttributeMaxDynamicSharedMemorySize, GEMM_SMEM_MAX);

    h16 *xb, *wqT, *wkT, *wvT, *woT, *w1Th, *w1Tl, *w3Th, *w3Tl, *w2Th, *w2Tl;
    h16 *qb, *kb, *vt, *pb, *attnb, *yh, *yl, *gh, *gl;
    float *q, *k, *v, *sc, *attn, *h, *f1, *f3;
    cudaGetSymbolAddress((void**)&xb,   g_xb);
    cudaGetSymbolAddress((void**)&wqT,  g_wqT);
    cudaGetSymbolAddress((void**)&wkT,  g_wkT);
    cudaGetSymbolAddress((void**)&wvT,  g_wvT);
    cudaGetSymbolAddress((void**)&woT,  g_woT);
    cudaGetSymbolAddress((void**)&w1Th, g_w1Th);
    cudaGetSymbolAddress((void**)&w1Tl, g_w1Tl);
    cudaGetSymbolAddress((void**)&w3Th, g_w3Th);
    cudaGetSymbolAddress((void**)&w3Tl, g_w3Tl);
    cudaGetSymbolAddress((void**)&w2Th, g_w2Th);
    cudaGetSymbolAddress((void**)&w2Tl, g_w2Tl);
    cudaGetSymbolAddress((void**)&q,    g_q);
    cudaGetSymbolAddress((void**)&k,    g_k);
    cudaGetSymbolAddress((void**)&v,    g_v);
    cudaGetSymbolAddress((void**)&qb,   g_qb);
    cudaGetSymbolAddress((void**)&kb,   g_kb);
    cudaGetSymbolAddress((void**)&vt,   g_vt);
    cudaGetSymbolAddress((void**)&sc,   g_sc);
    cudaGetSymbolAddress((void**)&pb,   g_pb);
    cudaGetSymbolAddress((void**)&attn, g_attn);
    cudaGetSymbolAddress((void**)&attnb,g_attnb);
    cudaGetSymbolAddress((void**)&h,    g_h);
    cudaGetSymbolAddress((void**)&yh,   g_yh);
    cudaGetSymbolAddress((void**)&yl,   g_yl);
    cudaGetSymbolAddress((void**)&f1,   g_f1);
    cudaGetSymbolAddress((void**)&f3,   g_f3);
    cudaGetSymbolAddress((void**)&gh,   g_gh);
    cudaGetSymbolAddress((void**)&gl,   g_gl);

    const long long SH  = (long long)SS * DD;
    const long long SSS = (long long)SS * SS;
    const float scale = 0.08838834764831845f;   // 1/sqrt(128)

    // weight prep
    { dim3 g(DD / 32, DD / 32);
      transpose_split<<<g, 256>>>(wq, wqT, nullptr, DD, DD);
      transpose_split<<<g, 256>>>(wk, wkT, nullptr, DD, DD);
      transpose_split<<<g, 256>>>(wv, wvT, nullptr, DD, DD);
      transpose_split<<<g, 256>>>(wo, woT, nullptr, DD, DD); }
    { dim3 g(FFD / 32, DD / 32);
      transpose_split<<<g, 256>>>(w1, w1Th, w1Tl, DD, FFD);
      transpose_split<<<g, 256>>>(w3, w3Th, w3Tl, DD, FFD); }
    { dim3 g(DD / 32, FFD / 32);
      transpose_split<<<g, 256>>>(w2, w2Th, w2Tl, FFD, DD); }

    // 1. x = rmsnorm(hidden) -> fp16
    rmsnorm_split<<<MM, 256>>>(hidden, anw, xb, nullptr);

    // 2. q/k/v = x @ W
    gemm(xb, nullptr, wqT, nullptr, nullptr, q, MM, DD, DD, DD, DD, DD, 0,
         1, 1, 0,0,0,0,0,0,0,0, 1.0f, 1, 0);
    gemm(xb, nullptr, wkT, nullptr, nullptr, k, MM, DD, DD, DD, DD, DD, 0,
         1, 1, 0,0,0,0,0,0,0,0, 1.0f, 1, 0);
    gemm(xb, nullptr, wvT, nullptr, nullptr, v, MM, DD, DD, DD, DD, DD, 0,
         1, 1, 0,0,0,0,0,0,0,0, 1.0f, 1, 0);

    // 3. rope -> fp16, v transpose -> fp16
    rope_h16<<<(unsigned)((long long)BBATCH * SS * HH * (DHH / 2) / 256), 256>>>(q, k, fcos, fsin, qb, kb);
    { dim3 g(SS / 32, DHH / 32, BBATCH * HH);
      v_transpose<<<g, 256>>>(v, vt); }

    // 4. scores = scale * q k^T (causal tile-skip)
    gemm(qb, nullptr, kb, nullptr, nullptr, sc, SS, SS, DHH,
         DD, DD, SS, 0, BBATCH * HH, HH,
         SH, DHH, SH, DHH, (long long)HH * SSS, SSS, 0, 0, scale, 1, 1);

    // 5. softmax -> fp16 probs
    { dim3 g(SS, BBATCH * HH);
      softmax_h16<<<g, 256>>>(sc, pb); }

    // 6. attn = probs @ v (K truncated at query block)
    gemm(pb, nullptr, vt, nullptr, nullptr, attn, SS, DHH, SS,
         SS, SS, DD, 0, BBATCH * HH, HH,
         (long long)HH * SSS, SSS, (long long)HH * DHH * SS, (long long)DHH * SS,
         SH, DHH, 0, 0, 1.0f, 1, 2);

    // 7. h = hidden + attn @ wo
    to_h16<<<(unsigned)((long long)MM * DD / 256), 256>>>(attn, attnb);
    gemm(attnb, nullptr, woT, nullptr, hidden, h, MM, DD, DD, DD, DD, DD, DD,
         1, 1, 0,0,0,0,0,0,0,0, 1.0f, 1, 0);

    // 8. y = rmsnorm(h) -> hi/lo
    rmsnorm_split<<<MM, 256>>>(h, fnw, yh, yl);

    // 9. FFN up (3-pass fp16x2)
    gemm(yh, yl, w1Th, w1Tl, nullptr, f1, MM, FFD, DD, DD, DD, FFD, 0,
         1, 1, 0,0,0,0,0,0,0,0, 1.0f, 3, 0);
    gemm(yh, yl, w3Th, w3Tl, nullptr, f3, MM, FFD, DD, DD, DD, FFD, 0,
         1, 1, 0,0,0,0,0,0,0,0, 1.0f, 3, 0);

    // 10. g = silu(f1)*f3 -> hi/lo
    silu_split<<<(unsigned)((long long)MM * FFD / 256), 256>>>(f1, f3, gh, gl);

    // 11. out = h + g @ w2 (3-pass fp16x2)
    gemm(gh, gl, w2Th, w2Tl, h, out, MM, DD, FFD, FFD, FFD, DD, DD,
         1, 1, 0,0,0,0,0,0,0,0, 1.0f, 3, 0);
}

// round 4
// speedup vs baseline: 6.6521x; 2.1994x over previous
#include <cuda_runtime.h>
#include <cuda_fp16.h>
#include <math.h>
#include <stdint.h>

#define BBATCH 2
#define SS 2048
#define DD 2048
#define HH 16
#define DHH 128
#define FFD 5632
#define MM (BBATCH * SS)
#define QKVN (3 * DD)        // 6144
#define F13N (2 * FFD)       // 11264

typedef __half h16;

// ------------------------- scratch (device globals) -------------------------
__device__ h16   g_xb   [(long long)MM * DD];
__device__ h16   g_wqkvT[(long long)QKVN * DD];
__device__ h16   g_woT  [(long long)DD * DD];
__device__ h16   g_w13T [(long long)F13N * DD];
__device__ h16   g_w2T  [(long long)DD * FFD];
__device__ float g_qkv  [(long long)MM * QKVN];
__device__ h16   g_qb   [(long long)MM * DD];
__device__ h16   g_kb   [(long long)MM * DD];
__device__ h16   g_vt   [(long long)BBATCH * HH * DHH * SS];
__device__ float g_sc   [(long long)BBATCH * HH * SS * SS];
__device__ h16   g_pb   [(long long)BBATCH * HH * SS * SS];
__device__ float g_attn [(long long)MM * DD];
__device__ h16   g_attnb[(long long)MM * DD];
__device__ float g_h    [(long long)MM * DD];
__device__ h16   g_yb   [(long long)MM * DD];
__device__ float g_f13  [(long long)MM * F13N];
__device__ h16   g_gb   [(long long)MM * FFD];

// ------------------------- helpers ------------------------------------------
__device__ __forceinline__ uint32_t smem_u32(const void* p) {
    uint32_t a;
    asm("{ .reg .u64 t; cvta.to.shared.u64 t, %1; cvt.u32.u64 %0, t; }" : "=r"(a) : "l"(p));
    return a;
}

__device__ __forceinline__ void cp_async16(uint32_t dst, const void* src) {
    asm volatile("cp.async.cg.shared.global [%0], [%1], 16;" :: "r"(dst), "l"(src));
}
__device__ __forceinline__ void cp_commit() {
    asm volatile("cp.async.commit_group;");
}
__device__ __forceinline__ void cp_wait1() {
    asm volatile("cp.async.wait_group 1;");
}

__device__ __forceinline__ void ldmx4(uint32_t* r, uint32_t addr) {
    asm volatile("ldmatrix.sync.aligned.m8n8.x4.shared.b16 {%0,%1,%2,%3}, [%4];"
                 : "=r"(r[0]), "=r"(r[1]), "=r"(r[2]), "=r"(r[3]) : "r"(addr));
}
__device__ __forceinline__ void ldmx2(uint32_t* r, uint32_t addr) {
    asm volatile("ldmatrix.sync.aligned.m8n8.x2.shared.b16 {%0,%1}, [%2];"
                 : "=r"(r[0]), "=r"(r[1]) : "r"(addr));
}
__device__ __forceinline__ void mma16816(float* c, const uint32_t* a, const uint32_t* b) {
    asm volatile(
        "mma.sync.aligned.m16n8k16.row.col.f32.f16.f16.f32 "
        "{%0,%1,%2,%3}, {%4,%5,%6,%7}, {%8,%9}, {%0,%1,%2,%3};"
        : "+f"(c[0]), "+f"(c[1]), "+f"(c[2]), "+f"(c[3])
        : "r"(a[0]), "r"(a[1]), "r"(a[2]), "r"(a[3]), "r"(b[0]), "r"(b[1]));
}

// ------------------------- HGEMM (mma.sync) ----------------------------------
// C[m][n] = alpha * sum_k A[m][k]*B[n][k] (+Res). A/B K-major fp16.
// CTA tile 128x128, BK=64, 3-stage cp.async pipeline, 8 warps (2m x 4n).
// stage layout (bytes): A @0 (16K), B @16K (16K). Stage = 32KB, 3 stages = 96KB.
__device__ __forceinline__ void stage_load(uint32_t sdst, const h16* g, int row0,
                                           long long ld, int k0, int tid)
{
    const int r = tid >> 1;                 // 0..127
    const int cb = (tid & 1) * 4;           // chunk base
    const h16* grow = g + (long long)(row0 + r) * ld + k0;
#pragma unroll
    for (int i = 0; i < 4; i++) {
        int c = cb + i;
        uint32_t dst = sdst + (uint32_t)(r * 128 + ((c ^ (r & 7)) * 16));
        cp_async16(dst, grow + c * 8);
    }
}

__global__ __launch_bounds__(256, 2)
void hgemm(const h16* __restrict__ A, const h16* __restrict__ B,
           const float* __restrict__ Res, float* __restrict__ C,
           int M, int N, int K,
           long long lda, long long ldb, long long ldc, long long ldres,
           int batchH,
           long long sAb, long long sAh, long long sBb, long long sBh,
           long long sCb, long long sCh,
           float alpha, int causal)
{
    extern __shared__ char smem[];

    const int m0 = blockIdx.y * 128;
    const int n0 = blockIdx.x * 128;
    if (causal == 1 && n0 > m0 + 127) return;
    int kEnd = K;
    if (causal == 2) kEnd = min(K, m0 + 128);

    const int z = blockIdx.z;
    const int bb = z / batchH;
    const int hh = z - bb * batchH;
    A += bb * sAb + hh * sAh;
    B += bb * sBb + hh * sBh;
    C += bb * sCb + hh * sCh;

    const int tid = threadIdx.x;
    const int lane = tid & 31;
    const int wid = tid >> 5;
    const int wm = wid >> 2;          // 0..1
    const int wn = wid & 3;           // 0..3

    const uint32_t sb = smem_u32(smem);
    const int KT = kEnd >> 6;

    const int nPro = (KT < 2) ? KT : 2;
    for (int s = 0; s < nPro; s++) {
        uint32_t base = sb + (uint32_t)(s % 3) * 32768u;
        stage_load(base, A, m0, lda, s * 64, tid);
        stage_load(base + 16384u, B, n0, ldb, s * 64, tid);
        cp_commit();
    }

    float acc[4][4][4];
#pragma unroll
    for (int i = 0; i < 4; i++)
#pragma unroll
        for (int j = 0; j < 4; j++)
#pragma unroll
            for (int q = 0; q < 4; q++) acc[i][j][q] = 0.0f;

    const int aRow = wm * 64 + (lane & 15);
    const int aKsel = lane >> 4;
    const int aSwz = aRow & 7;
    const int bRowBase = wn * 32 + (lane & 7);
    const int bKsel = (lane >> 3) & 1;

    for (int s = 0; s < KT; s++) {
        cp_wait1();
        __syncthreads();
        if (s + 2 < KT) {
            uint32_t base = sb + (uint32_t)((s + 2) % 3) * 32768u;
            stage_load(base, A, m0, lda, (s + 2) * 64, tid);
            stage_load(base + 16384u, B, n0, ldb, (s + 2) * 64, tid);
        }
        cp_commit();

        const uint32_t base = sb + (uint32_t)(s % 3) * 32768u;
#pragma unroll
        for (int kc = 0; kc < 4; kc++) {
            uint32_t a[4][4], b[4][2];
#pragma unroll
            for (int mt = 0; mt < 4; mt++) {
                uint32_t ad = base + (uint32_t)((aRow + mt * 16) * 128 +
                              (((kc * 2 + aKsel) ^ aSwz) * 16));
                ldmx4(a[mt], ad);
            }
#pragma unroll
            for (int nt = 0; nt < 4; nt++) {
                int nRow = bRowBase + nt * 8;
                uint32_t bd = base + 16384u + (uint32_t)(nRow * 128 +
                              (((kc * 2 + bKsel) ^ (nRow & 7)) * 16));
                ldmx2(b[nt], bd);
            }
#pragma unroll
            for (int mt = 0; mt < 4; mt++)
#pragma unroll
                for (int nt = 0; nt < 4; nt++)
                    mma16816(acc[mt][nt], a[mt], b[nt]);
        }
        __syncthreads();
    }

#pragma unroll
    for (int mt = 0; mt < 4; mt++) {
#pragma unroll
        for (int nt = 0; nt < 4; nt++) {
            const int m = m0 + wm * 64 + mt * 16 + (lane >> 2);
            const int n = n0 + wn * 32 + nt * 8 + (lane & 3) * 2;
            float2 v0, v1;
            v0.x = acc[mt][nt][0] * alpha; v0.y = acc[mt][nt][1] * alpha;
            v1.x = acc[mt][nt][2] * alpha; v1.y = acc[mt][nt][3] * alpha;
            if (Res) {
                float2 r0 = *reinterpret_cast<const float2*>(&Res[(long long)m * ldres + n]);
                float2 r1 = *reinterpret_cast<const float2*>(&Res[(long long)(m + 8) * ldres + n]);
                v0.x += r0.x; v0.y += r0.y; v1.x += r1.x; v1.y += r1.y;
            }
            *reinterpret_cast<float2*>(&C[(long long)m * ldc + n]) = v0;
            *reinterpret_cast<float2*>(&C[(long long)(m + 8) * ldc + n]) = v1;
        }
    }
}

// ------------------------- elementwise kernels --------------------------------
__global__ __launch_bounds__(256)
void rmsnorm_h16(const float* __restrict__ in, const float* __restrict__ w,
                 h16* __restrict__ o)
{
    __shared__ float red[256];
    const long long row = blockIdx.x;
    const float* p = in + row * DD;
    const int tid = threadIdx.x;
    float v[8];
    float ss = 0.0f;
#pragma unroll
    for (int t = 0; t < 8; t++) { v[t] = p[tid + t * 256]; ss += v[t] * v[t]; }
    red[tid] = ss;
    __syncthreads();
    for (int s = 128; s > 0; s >>= 1) {
        if (tid < s) red[tid] += red[tid + s];
        __syncthreads();
    }
    const float scale = rsqrtf(red[0] / (float)DD + 1e-6f);
#pragma unroll
    for (int t = 0; t < 8; t++) {
        int j = tid + t * 256;
        o[row * DD + j] = __float2half_rn(v[t] * scale * w[j]);
    }
}

// W [K,N] fp32 -> WT [N,K] fp16
__global__ __launch_bounds__(256)
void transpose_h16(const float* __restrict__ W, h16* __restrict__ out, int K, int N)
{
    __shared__ float t[32][33];
    const int k0 = blockIdx.y * 32, n0 = blockIdx.x * 32;
    const int tx = threadIdx.x & 31, ty = threadIdx.x >> 5;
#pragma unroll
    for (int i = 0; i < 32; i += 8)
        t[ty + i][tx] = W[(long long)(k0 + ty + i) * N + n0 + tx];
    __syncthreads();
#pragma unroll
    for (int i = 0; i < 32; i += 8)
        out[(long long)(n0 + ty + i) * K + k0 + tx] = __float2half_rn(t[tx][ty + i]);
}

// rope reads q,k out of combined qkv [MM, 6144]
__global__ __launch_bounds__(256)
void rope_h16(const float* __restrict__ qkv,
              const float* __restrict__ fcos, const float* __restrict__ fsin,
              h16* __restrict__ qb, h16* __restrict__ kb)
{
    long long idx = (long long)blockIdx.x * 256 + threadIdx.x; // B*S*H*64
    const int HALF = DHH / 2;
    int i = idx & (HALF - 1);
    long long t = idx >> 6;
    int h = t & (HH - 1);
    t >>= 4;
    int s = t & (SS - 1);
    long long b = t >> 11;
    const long long m = b * SS + s;
    const long long src = m * QKVN + h * DHH + 2 * i;
    const long long dst = m * DD + h * DHH + 2 * i;

    float c  = fcos[(long long)s * HALF + i];
    float sn = fsin[(long long)s * HALF + i];

    float xr = qkv[src], xi = qkv[src + 1];
    qb[dst]     = __float2half_rn(xr * c - xi * sn);
    qb[dst + 1] = __float2half_rn(xr * sn + xi * c);
    xr = qkv[src + DD]; xi = qkv[src + DD + 1];
    kb[dst]     = __float2half_rn(xr * c - xi * sn);
    kb[dst + 1] = __float2half_rn(xr * sn + xi * c);
}

// v (cols 4096.. of qkv) -> vt [B,H,DH,S] fp16
__global__ __launch_bounds__(256)
void v_transpose(const float* __restrict__ qkv, h16* __restrict__ vt)
{
    __shared__ float t[32][33];
    const int z = blockIdx.z;
    const int b = z >> 4, h = z & 15;
    const float* src = qkv + (long long)b * SS * QKVN + 2 * DD + h * DHH;
    h16* dst = vt + (long long)z * DHH * SS;
    const int s0 = blockIdx.x * 32, d0 = blockIdx.y * 32;
    const int tx = threadIdx.x & 31, ty = threadIdx.x >> 5;
#pragma unroll
    for (int i = 0; i < 32; i += 8)
        t[ty + i][tx] = src[(long long)(s0 + ty + i) * QKVN + d0 + tx];
    __syncthreads();
#pragma unroll
    for (int i = 0; i < 32; i += 8)
        dst[(long long)(d0 + ty + i) * SS + s0 + tx] = __float2half_rn(t[tx][ty + i]);
}

__global__ __launch_bounds__(256)
void softmax_h16(const float* __restrict__ sc, h16* __restrict__ pb)
{
    __shared__ float red[256];
    const int row = blockIdx.x;
    const int bh  = blockIdx.y;
    const float* p = sc + ((long long)bh * SS + row) * (long long)SS;
    h16* o = pb + ((long long)bh * SS + row) * (long long)SS;
    const int n = row + 1;
    const int lim = (row & ~127) + 128;     // PV only reads keys < lim
    const int tid = threadIdx.x;

    float v[8];
    float mx = -3.402823e38f;
#pragma unroll
    for (int t = 0; t < 8; t++) {
        int j = tid + t * 256;
        if (j < n) { v[t] = p[j]; mx = fmaxf(mx, v[t]); }
    }
    red[tid] = mx;
    __syncthreads();
    for (int s = 128; s > 0; s >>= 1) {
        if (tid < s) red[tid] = fmaxf(red[tid], red[tid + s]);
        __syncthreads();
    }
    mx = red[0];
    __syncthreads();
    float sum = 0.0f;
#pragma unroll
    for (int t = 0; t < 8; t++) {
        int j = tid + t * 256;
        if (j < n) { v[t] = __expf(v[t] - mx); sum += v[t]; }
    }
    red[tid] = sum;
    __syncthreads();
    for (int s = 128; s > 0; s >>= 1) {
        if (tid < s) red[tid] += red[tid + s];
        __syncthreads();
    }
    const float inv = 1.0f / red[0];
#pragma unroll
    for (int t = 0; t < 8; t++) {
        int j = tid + t * 256;
        if (j < lim) o[j] = __float2half_rn((j < n) ? v[t] * inv : 0.0f);
    }
}

__global__ __launch_bounds__(256)
void to_h16(const float* __restrict__ in, h16* __restrict__ o)
{
    long long i = (long long)blockIdx.x * 256 + threadIdx.x;
    o[i] = __float2half_rn(in[i]);
}

// g = silu(f13[:, :FFD]) * f13[:, FFD:]
__global__ __launch_bounds__(256)
void silu_h16(const float* __restrict__ f13, h16* __restrict__ o)
{
    long long i = (long long)blockIdx.x * 256 + threadIdx.x;  // over MM*FFD
    long long m = i / FFD;
    long long j = i - m * FFD;
    const float* row = f13 + m * F13N;
    float a = row[j];
    float g = (a / (1.0f + __expf(-a))) * row[j + FFD];
    o[i] = __float2half_rn(g);
}

// ------------------------- host ----------------------------------------------
#define GEMM_SMEM (3 * 32768)

static void gemm(const h16* A, const h16* B, const float* Res, float* C,
                 int M, int N, int K,
                 long long lda, long long ldb, long long ldc, long long ldres,
                 int nbatch, int batchH,
                 long long sAb, long long sAh, long long sBb, long long sBh,
                 long long sCb, long long sCh,
                 float alpha, int causal)
{
    dim3 grid(N / 128, M / 128, nbatch);
    hgemm<<<grid, 256, GEMM_SMEM>>>(A, B, Res, C, M, N, K,
                                    lda, ldb, ldc, ldres, batchH,
                                    sAb, sAh, sBb, sBh, sCb, sCh,
                                    alpha, causal);
}

extern "C" void kernel_launch(void* const* d_in, const int* in_sizes, int n_in,
                              void* d_out, int out_size)
{
    (void)in_sizes; (void)n_in; (void)out_size;
    const float* hidden = (const float*)d_in[0];
    const float* fcos   = (const float*)d_in[1];
    const float* fsin   = (const float*)d_in[2];
    const float* wq     = (const float*)d_in[3];
    const float* wk     = (const float*)d_in[4];
    const float* wv     = (const float*)d_in[5];
    const float* wo     = (const float*)d_in[6];
    const float* w1     = (const float*)d_in[7];
    const float* w2     = (const float*)d_in[8];
    const float* w3     = (const float*)d_in[9];
    const float* anw    = (const float*)d_in[10];
    const float* fnw    = (const float*)d_in[11];
    float* out = (float*)d_out;

    cudaFuncSetAttribute(hgemm, cudaFuncAttributeMaxDynamicSharedMemorySize, GEMM_SMEM);

    h16 *xb, *wqkvT, *woT, *w13T, *w2T, *qb, *kb, *vt, *pb, *attnb, *yb, *gb;
    float *qkv, *sc, *attn, *h, *f13;
    cudaGetSymbolAddress((void**)&xb,    g_xb);
    cudaGetSymbolAddress((void**)&wqkvT, g_wqkvT);
    cudaGetSymbolAddress((void**)&woT,   g_woT);
    cudaGetSymbolAddress((void**)&w13T,  g_w13T);
    cudaGetSymbolAddress((void**)&w2T,   g_w2T);
    cudaGetSymbolAddress((void**)&qkv,   g_qkv);
    cudaGetSymbolAddress((void**)&qb,    g_qb);
    cudaGetSymbolAddress((void**)&kb,    g_kb);
    cudaGetSymbolAddress((void**)&vt,    g_vt);
    cudaGetSymbolAddress((void**)&sc,    g_sc);
    cudaGetSymbolAddress((void**)&pb,    g_pb);
    cudaGetSymbolAddress((void**)&attn,  g_attn);
    cudaGetSymbolAddress((void**)&attnb, g_attnb);
    cudaGetSymbolAddress((void**)&h,     g_h);
    cudaGetSymbolAddress((void**)&yb,    g_yb);
    cudaGetSymbolAddress((void**)&f13,   g_f13);
    cudaGetSymbolAddress((void**)&gb,    g_gb);

    const long long SH  = (long long)SS * DD;
    const long long SSS = (long long)SS * SS;
    const float scale = 0.08838834764831845f;   // 1/sqrt(128)

    // weight prep (fp32 -> fp16, transposed to [N,K])
    { dim3 g(DD / 32, DD / 32);
      transpose_h16<<<g, 256>>>(wq, wqkvT,               DD, DD);
      transpose_h16<<<g, 256>>>(wk, wqkvT + (long long)DD * DD,     DD, DD);
      transpose_h16<<<g, 256>>>(wv, wqkvT + (long long)2 * DD * DD, DD, DD);
      transpose_h16<<<g, 256>>>(wo, woT, DD, DD); }
    { dim3 g(FFD / 32, DD / 32);
      transpose_h16<<<g, 256>>>(w1, w13T, DD, FFD);
      transpose_h16<<<g, 256>>>(w3, w13T + (long long)FFD * DD, DD, FFD); }
    { dim3 g(DD / 32, FFD / 32);
      transpose_h16<<<g, 256>>>(w2, w2T, FFD, DD); }

    // 1. x = rmsnorm(hidden) -> fp16
    rmsnorm_h16<<<MM, 256>>>(hidden, anw, xb);

    // 2. qkv = x @ [wq|wk|wv]   (4096 x 6144 x 2048)
    gemm(xb, wqkvT, nullptr, qkv, MM, QKVN, DD, DD, DD, QKVN, 0,
         1, 1, 0,0,0,0,0,0, 1.0f, 0);

    // 3. rope -> fp16, v transpose -> fp16
    rope_h16<<<(unsigned)((long long)BBATCH * SS * HH * (DHH / 2) / 256), 256>>>(qkv, fcos, fsin, qb, kb);
    { dim3 g(SS / 32, DHH / 32, BBATCH * HH);
      v_transpose<<<g, 256>>>(qkv, vt); }

    // 4. scores = scale * q k^T (causal tile-skip)
    gemm(qb, kb, nullptr, sc, SS, SS, DHH,
         DD, DD, SS, 0, BBATCH * HH, HH,
         SH, DHH, SH, DHH, (long long)HH * SSS, SSS, scale, 1);

    // 5. softmax -> fp16 probs
    { dim3 g(SS, BBATCH * HH);
      softmax_h16<<<g, 256>>>(sc, pb); }

    // 6. attn = probs @ v (K truncated at query block)
    gemm(pb, vt, nullptr, attn, SS, DHH, SS,
         SS, SS, DD, 0, BBATCH * HH, HH,
         (long long)HH * SSS, SSS, (long long)HH * DHH * SS, (long long)DHH * SS,
         SH, DHH, 1.0f, 2);

    // 7. h = hidden + attn @ wo
    to_h16<<<(unsigned)((long long)MM * DD / 256), 256>>>(attn, attnb);
    gemm(attnb, woT, hidden, h, MM, DD, DD, DD, DD, DD, DD,
         1, 1, 0,0,0,0,0,0, 1.0f, 0);

    // 8. y = rmsnorm(h) -> fp16
    rmsnorm_h16<<<MM, 256>>>(h, fnw, yb);

    // 9. f13 = y @ [w1|w3]   (4096 x 11264 x 2048)
    gemm(yb, w13T, nullptr, f13, MM, F13N, DD, DD, DD, F13N, 0,
         1, 1, 0,0,0,0,0,0, 1.0f, 0);

    // 10. g = silu(f1)*f3 -> fp16
    silu_h16<<<(unsigned)((long long)MM * FFD / 256), 256>>>(f13, gb);

    // 11. out = h + g @ w2
    gemm(gb, w2T, h, out, MM, DD, FFD, FFD, FFD, DD, DD,
         1, 1, 0,0,0,0,0,0, 1.0f, 0);
}

// round 5
// speedup vs baseline: 7.7263x; 1.1615x over previous
#include <cuda_runtime.h>
#include <cuda_fp16.h>
#include <math.h>
#include <stdint.h>

#define BBATCH 2
#define SS 2048
#define DD 2048
#define HH 16
#define DHH 128
#define FFD 5632
#define MM (BBATCH * SS)
#define QKVN (3 * DD)        // 6144
#define F13N (2 * FFD)       // 11264

typedef __half h16;

// ------------------------- scratch (device globals) -------------------------
__device__ h16   g_xb   [(long long)MM * DD];
__device__ h16   g_wqkvT[(long long)QKVN * DD];
__device__ h16   g_woT  [(long long)DD * DD];
__device__ h16   g_w13T [(long long)F13N * DD];
__device__ h16   g_w2T  [(long long)DD * FFD];
__device__ h16   g_qkvh [(long long)MM * QKVN];
__device__ h16   g_qb   [(long long)MM * DD];
__device__ h16   g_kb   [(long long)MM * DD];
__device__ h16   g_vt   [(long long)BBATCH * HH * DHH * SS];
__device__ h16   g_attnb[(long long)MM * DD];
__device__ float g_h    [(long long)MM * DD];
__device__ h16   g_yb   [(long long)MM * DD];
__device__ h16   g_f13h [(long long)MM * F13N];
__device__ h16   g_gb   [(long long)MM * FFD];

// ------------------------- helpers ------------------------------------------
__device__ __forceinline__ uint32_t smem_u32(const void* p) {
    uint32_t a;
    asm("{ .reg .u64 t; cvta.to.shared.u64 t, %1; cvt.u32.u64 %0, t; }" : "=r"(a) : "l"(p));
    return a;
}

__device__ __forceinline__ void cp_async16(uint32_t dst, const void* src) {
    asm volatile("cp.async.cg.shared.global [%0], [%1], 16;" :: "r"(dst), "l"(src));
}
__device__ __forceinline__ void cp_commit() {
    asm volatile("cp.async.commit_group;");
}
__device__ __forceinline__ void cp_wait1() {
    asm volatile("cp.async.wait_group 1;");
}
__device__ __forceinline__ void cp_wait0() {
    asm volatile("cp.async.wait_group 0;");
}

__device__ __forceinline__ void ldmx4(uint32_t* r, uint32_t addr) {
    asm volatile("ldmatrix.sync.aligned.m8n8.x4.shared.b16 {%0,%1,%2,%3}, [%4];"
                 : "=r"(r[0]), "=r"(r[1]), "=r"(r[2]), "=r"(r[3]) : "r"(addr));
}
__device__ __forceinline__ void ldmx2(uint32_t* r, uint32_t addr) {
    asm volatile("ldmatrix.sync.aligned.m8n8.x2.shared.b16 {%0,%1}, [%2];"
                 : "=r"(r[0]), "=r"(r[1]) : "r"(addr));
}
__device__ __forceinline__ void mma16816(float* c, const uint32_t* a, const uint32_t* b) {
    asm volatile(
        "mma.sync.aligned.m16n8k16.row.col.f32.f16.f16.f32 "
        "{%0,%1,%2,%3}, {%4,%5,%6,%7}, {%8,%9}, {%0,%1,%2,%3};"
        : "+f"(c[0]), "+f"(c[1]), "+f"(c[2]), "+f"(c[3])
        : "r"(a[0]), "r"(a[1]), "r"(a[2]), "r"(a[3]), "r"(b[0]), "r"(b[1]));
}
__device__ __forceinline__ uint32_t packh2(float a, float b) {
    __half2 h = __floats2half2_rn(a, b);
    return *reinterpret_cast<uint32_t*>(&h);
}

// ------------------------- HGEMM (mma.sync) ----------------------------------
// C[m][n] = alpha * sum_k A[m][k]*B[n][k] (+Res). A/B K-major fp16.
// CTA tile 128x128, BK=64, 3-stage cp.async pipeline, 8 warps (2m x 4n).
__device__ __forceinline__ void stage_load(uint32_t sdst, const h16* g, int row0,
                                           long long ld, int k0, int tid)
{
    const int r = tid >> 1;
    const int cb = (tid & 1) * 4;
    const h16* grow = g + (long long)(row0 + r) * ld + k0;
#pragma unroll
    for (int i = 0; i < 4; i++) {
        int c = cb + i;
        uint32_t dst = sdst + (uint32_t)(r * 128 + ((c ^ (r & 7)) * 16));
        cp_async16(dst, grow + c * 8);
    }
}

__global__ __launch_bounds__(256, 2)
void hgemm(const h16* __restrict__ A, const h16* __restrict__ B,
           const float* __restrict__ Res, float* __restrict__ C,
           h16* __restrict__ C16,
           int M, int N, int K,
           long long lda, long long ldb, long long ldc, long long ldres,
           float alpha)
{
    extern __shared__ char smem[];

    const int m0 = blockIdx.y * 128;
    const int n0 = blockIdx.x * 128;

    const int tid = threadIdx.x;
    const int lane = tid & 31;
    const int wid = tid >> 5;
    const int wm = wid >> 2;
    const int wn = wid & 3;

    const uint32_t sb = smem_u32(smem);
    const int KT = K >> 6;

    const int nPro = (KT < 2) ? KT : 2;
    for (int s = 0; s < nPro; s++) {
        uint32_t base = sb + (uint32_t)(s % 3) * 32768u;
        stage_load(base, A, m0, lda, s * 64, tid);
        stage_load(base + 16384u, B, n0, ldb, s * 64, tid);
        cp_commit();
    }

    float acc[4][4][4];
#pragma unroll
    for (int i = 0; i < 4; i++)
#pragma unroll
        for (int j = 0; j < 4; j++)
#pragma unroll
            for (int q = 0; q < 4; q++) acc[i][j][q] = 0.0f;

    const int aRow = wm * 64 + (lane & 15);
    const int aKsel = lane >> 4;
    const int aSwz = aRow & 7;
    const int bRowBase = wn * 32 + (lane & 7);
    const int bKsel = (lane >> 3) & 1;

    for (int s = 0; s < KT; s++) {
        cp_wait1();
        __syncthreads();
        if (s + 2 < KT) {
            uint32_t base = sb + (uint32_t)((s + 2) % 3) * 32768u;
            stage_load(base, A, m0, lda, (s + 2) * 64, tid);
            stage_load(base + 16384u, B, n0, ldb, (s + 2) * 64, tid);
        }
        cp_commit();

        const uint32_t base = sb + (uint32_t)(s % 3) * 32768u;
#pragma unroll
        for (int kc = 0; kc < 4; kc++) {
            uint32_t a[4][4], b[4][2];
#pragma unroll
            for (int mt = 0; mt < 4; mt++) {
                uint32_t ad = base + (uint32_t)((aRow + mt * 16) * 128 +
                              (((kc * 2 + aKsel) ^ aSwz) * 16));
                ldmx4(a[mt], ad);
            }
#pragma unroll
            for (int nt = 0; nt < 4; nt++) {
                int nRow = bRowBase + nt * 8;
                uint32_t bd = base + 16384u + (uint32_t)(nRow * 128 +
                              (((kc * 2 + bKsel) ^ (nRow & 7)) * 16));
                ldmx2(b[nt], bd);
            }
#pragma unroll
            for (int mt = 0; mt < 4; mt++)
#pragma unroll
                for (int nt = 0; nt < 4; nt++)
                    mma16816(acc[mt][nt], a[mt], b[nt]);
        }
        __syncthreads();
    }

#pragma unroll
    for (int mt = 0; mt < 4; mt++) {
#pragma unroll
        for (int nt = 0; nt < 4; nt++) {
            const int m = m0 + wm * 64 + mt * 16 + (lane >> 2);
            const int n = n0 + wn * 32 + nt * 8 + (lane & 3) * 2;
            if (C16) {
                uint32_t h0 = packh2(acc[mt][nt][0] * alpha, acc[mt][nt][1] * alpha);
                uint32_t h1 = packh2(acc[mt][nt][2] * alpha, acc[mt][nt][3] * alpha);
                *reinterpret_cast<uint32_t*>(&C16[(long long)m * ldc + n]) = h0;
                *reinterpret_cast<uint32_t*>(&C16[(long long)(m + 8) * ldc + n]) = h1;
            } else {
                float2 v0, v1;
                v0.x = acc[mt][nt][0] * alpha; v0.y = acc[mt][nt][1] * alpha;
                v1.x = acc[mt][nt][2] * alpha; v1.y = acc[mt][nt][3] * alpha;
                if (Res) {
                    float2 r0 = *reinterpret_cast<const float2*>(&Res[(long long)m * ldres + n]);
                    float2 r1 = *reinterpret_cast<const float2*>(&Res[(long long)(m + 8) * ldres + n]);
                    v0.x += r0.x; v0.y += r0.y; v1.x += r1.x; v1.y += r1.y;
                }
                *reinterpret_cast<float2*>(&C[(long long)m * ldc + n]) = v0;
                *reinterpret_cast<float2*>(&C[(long long)(m + 8) * ldc + n]) = v1;
            }
        }
    }
}

// ------------------------- fused flash attention ------------------------------
// Grid: (SS/128, B*H). 8 warps; warp handles 16 query rows.
// smem: q 32KB @0; kv buffers @32768 + buf*65536 (k @+0, v @+32768).
#define FA_SMEM (32768 + 2 * 65536)
#define SM_SCALE 0.08838834764831845f

__global__ __launch_bounds__(256, 1)
void flash_attn(const h16* __restrict__ qg, const h16* __restrict__ kg,
                const h16* __restrict__ vtg, h16* __restrict__ og)
{
    extern __shared__ char smem[];
    const int qt = blockIdx.x;
    const int bh = blockIdx.y;
    const int b = bh >> 4, h = bh & 15;

    const h16* qp = qg + (long long)b * SS * DD + h * DHH;
    const h16* kp = kg + (long long)b * SS * DD + h * DHH;
    const h16* vp = vtg + (long long)bh * DHH * SS;

    const int tid = threadIdx.x;
    const int lane = tid & 31;
    const int wid = tid >> 5;
    const int wrow = wid * 16;

    const uint32_t sb = smem_u32(smem);
    const uint32_t qbs = sb;

    // load q tile (2 subtiles of [128][64])
    stage_load(qbs, qp, qt * 128, DD, 0, tid);
    stage_load(qbs + 16384u, qp, qt * 128, DD, 64, tid);
    cp_commit();
    // load kv tile 0
    {
        uint32_t kvb = sb + 32768u;
        stage_load(kvb, kp, 0, DD, 0, tid);
        stage_load(kvb + 16384u, kp, 0, DD, 64, tid);
        stage_load(kvb + 32768u, vp, 0, SS, 0, tid);
        stage_load(kvb + 49152u, vp, 0, SS, 64, tid);
        cp_commit();
    }

    // fragment address pieces
    const int aRow = wrow + (lane & 15);
    const int aKsel = lane >> 4;
    const int aSwz = aRow & 7;
    const int bRow7 = lane & 7;
    const int bNtSel = (lane >> 4) & 1;    // which n-tile of the pair
    const int bKsel = (lane >> 3) & 1;

    uint32_t aq[8][4];
    float o[16][4];
    float mrow[2], lrow[2];
#pragma unroll
    for (int i = 0; i < 16; i++)
#pragma unroll
        for (int j = 0; j < 4; j++) o[i][j] = 0.0f;
    mrow[0] = mrow[1] = -1e30f;
    lrow[0] = lrow[1] = 0.0f;

    const int nKT = qt + 1;
    for (int kt = 0; kt < nKT; kt++) {
        cp_wait0();
        __syncthreads();
        const uint32_t kvb = sb + 32768u + (uint32_t)(kt & 1) * 65536u;
        if (kt + 1 < nKT) {
            uint32_t nb = sb + 32768u + (uint32_t)((kt + 1) & 1) * 65536u;
            stage_load(nb, kp, (kt + 1) * 128, DD, 0, tid);
            stage_load(nb + 16384u, kp, (kt + 1) * 128, DD, 64, tid);
            stage_load(nb + 32768u, vp, 0, SS, (kt + 1) * 128, tid);
            stage_load(nb + 49152u, vp, 0, SS, (kt + 1) * 128 + 64, tid);
            cp_commit();
        }
        if (kt == 0) {
#pragma unroll
            for (int kc = 0; kc < 8; kc++) {
                uint32_t base = qbs + (kc >= 4 ? 16384u : 0u);
                uint32_t ad = base + (uint32_t)(aRow * 128 +
                              ((((kc & 3) * 2 + aKsel) ^ aSwz) * 16));
                ldmx4(aq[kc], ad);
            }
        }

        // ---- S = q k^T (16 n-tiles of 8 keys)
        float s[16][4];
#pragma unroll
        for (int i = 0; i < 16; i++)
#pragma unroll
            for (int j = 0; j < 4; j++) s[i][j] = 0.0f;
#pragma unroll
        for (int ntp = 0; ntp < 8; ntp++) {
#pragma unroll
            for (int kc = 0; kc < 8; kc++) {
                uint32_t base = kvb + (kc >= 4 ? 16384u : 0u);
                int nRow = (ntp * 2 + bNtSel) * 8 + bRow7;
                uint32_t bd = base + (uint32_t)(nRow * 128 +
                              ((((kc & 3) * 2 + bKsel) ^ (nRow & 7)) * 16));
                uint32_t bv[4];
                ldmx4(bv, bd);
                mma16816(s[ntp * 2],     aq[kc], bv);
                mma16816(s[ntp * 2 + 1], aq[kc], bv + 2);
            }
        }

        // ---- causal mask on diagonal tile
        if (kt == qt) {
            const int ii0 = wrow + (lane >> 2);
#pragma unroll
            for (int nt = 0; nt < 16; nt++) {
                int jj = nt * 8 + 2 * (lane & 3);
                if (jj > ii0)      s[nt][0] = -1e30f;
                if (jj + 1 > ii0)  s[nt][1] = -1e30f;
                if (jj > ii0 + 8)     s[nt][2] = -1e30f;
                if (jj + 1 > ii0 + 8) s[nt][3] = -1e30f;
            }
        }

        // ---- online softmax
        float mx0 = -1e30f, mx1 = -1e30f;
#pragma unroll
        for (int nt = 0; nt < 16; nt++) {
            mx0 = fmaxf(mx0, fmaxf(s[nt][0], s[nt][1]));
            mx1 = fmaxf(mx1, fmaxf(s[nt][2], s[nt][3]));
        }
        mx0 = fmaxf(mx0, __shfl_xor_sync(0xffffffffu, mx0, 1));
        mx0 = fmaxf(mx0, __shfl_xor_sync(0xffffffffu, mx0, 2));
        mx1 = fmaxf(mx1, __shfl_xor_sync(0xffffffffu, mx1, 1));
        mx1 = fmaxf(mx1, __shfl_xor_sync(0xffffffffu, mx1, 2));
        const float mn0 = fmaxf(mrow[0], mx0);
        const float mn1 = fmaxf(mrow[1], mx1);
        const float f0 = __expf((mrow[0] - mn0) * SM_SCALE);
        const float f1 = __expf((mrow[1] - mn1) * SM_SCALE);
        mrow[0] = mn0; mrow[1] = mn1;
#pragma unroll
        for (int nt = 0; nt < 16; nt++) {
            o[nt][0] *= f0; o[nt][1] *= f0;
            o[nt][2] *= f1; o[nt][3] *= f1;
        }
        float sum0 = 0.0f, sum1 = 0.0f;
#pragma unroll
        for (int nt = 0; nt < 16; nt++) {
            s[nt][0] = __expf((s[nt][0] - mn0) * SM_SCALE);
            s[nt][1] = __expf((s[nt][1] - mn0) * SM_SCALE);
            s[nt][2] = __expf((s[nt][2] - mn1) * SM_SCALE);
            s[nt][3] = __expf((s[nt][3] - mn1) * SM_SCALE);
            sum0 += s[nt][0] + s[nt][1];
            sum1 += s[nt][2] + s[nt][3];
        }
        sum0 += __shfl_xor_sync(0xffffffffu, sum0, 1);
        sum0 += __shfl_xor_sync(0xffffffffu, sum0, 2);
        sum1 += __shfl_xor_sync(0xffffffffu, sum1, 1);
        sum1 += __shfl_xor_sync(0xffffffffu, sum1, 2);
        lrow[0] = lrow[0] * f0 + sum0;
        lrow[1] = lrow[1] * f1 + sum1;

        // ---- O += P V  (keys are the k-dim; vt tile [dh][keys])
#pragma unroll
        for (int kc = 0; kc < 8; kc++) {
            uint32_t ap[4];
            ap[0] = packh2(s[kc * 2][0], s[kc * 2][1]);
            ap[1] = packh2(s[kc * 2][2], s[kc * 2][3]);
            ap[2] = packh2(s[kc * 2 + 1][0], s[kc * 2 + 1][1]);
            ap[3] = packh2(s[kc * 2 + 1][2], s[kc * 2 + 1][3]);
#pragma unroll
            for (int ntp = 0; ntp < 8; ntp++) {
                uint32_t base = kvb + 32768u + (kc >= 4 ? 16384u : 0u);
                int nRow = (ntp * 2 + bNtSel) * 8 + bRow7;
                uint32_t bd = base + (uint32_t)(nRow * 128 +
                              ((((kc & 3) * 2 + bKsel) ^ (nRow & 7)) * 16));
                uint32_t bv[4];
                ldmx4(bv, bd);
                mma16816(o[ntp * 2],     ap, bv);
                mma16816(o[ntp * 2 + 1], ap, bv + 2);
            }
        }
    }

    // ---- normalize and store fp16
    const float inv0 = 1.0f / lrow[0];
    const float inv1 = 1.0f / lrow[1];
    const long long row0 = (long long)b * SS + qt * 128 + wrow + (lane >> 2);
#pragma unroll
    for (int nt = 0; nt < 16; nt++) {
        int dcol = h * DHH + nt * 8 + 2 * (lane & 3);
        uint32_t h0 = packh2(o[nt][0] * inv0, o[nt][1] * inv0);
        uint32_t h1 = packh2(o[nt][2] * inv1, o[nt][3] * inv1);
        *reinterpret_cast<uint32_t*>(&og[row0 * DD + dcol]) = h0;
        *reinterpret_cast<uint32_t*>(&og[(row0 + 8) * DD + dcol]) = h1;
    }
}

// ------------------------- elementwise kernels --------------------------------
__global__ __launch_bounds__(256)
void rmsnorm_h16(const float* __restrict__ in, const float* __restrict__ w,
                 h16* __restrict__ o)
{
    __shared__ float red[256];
    const long long row = blockIdx.x;
    const float* p = in + row * DD;
    const int tid = threadIdx.x;
    float v[8];
    float ss = 0.0f;
#pragma unroll
    for (int t = 0; t < 8; t++) { v[t] = p[tid + t * 256]; ss += v[t] * v[t]; }
    red[tid] = ss;
    __syncthreads();
    for (int s = 128; s > 0; s >>= 1) {
        if (tid < s) red[tid] += red[tid + s];
        __syncthreads();
    }
    const float scale = rsqrtf(red[0] / (float)DD + 1e-6f);
#pragma unroll
    for (int t = 0; t < 8; t++) {
        int j = tid + t * 256;
        o[row * DD + j] = __float2half_rn(v[t] * scale * w[j]);
    }
}

// W [K,N] fp32 -> WT [N,K] fp16
__global__ __launch_bounds__(256)
void transpose_h16(const float* __restrict__ W, h16* __restrict__ out, int K, int N)
{
    __shared__ float t[32][33];
    const int k0 = blockIdx.y * 32, n0 = blockIdx.x * 32;
    const int tx = threadIdx.x & 31, ty = threadIdx.x >> 5;
#pragma unroll
    for (int i = 0; i < 32; i += 8)
        t[ty + i][tx] = W[(long long)(k0 + ty + i) * N + n0 + tx];
    __syncthreads();
#pragma unroll
    for (int i = 0; i < 32; i += 8)
        out[(long long)(n0 + ty + i) * K + k0 + tx] = __float2half_rn(t[tx][ty + i]);
}

// rope on combined fp16 qkv [MM, 6144]
__global__ __launch_bounds__(256)
void rope_h16(const h16* __restrict__ qkv,
              const float* __restrict__ fcos, const float* __restrict__ fsin,
              h16* __restrict__ qb, h16* __restrict__ kb)
{
    long long idx = (long long)blockIdx.x * 256 + threadIdx.x;
    const int HALF = DHH / 2;
    int i = idx & (HALF - 1);
    long long t = idx >> 6;
    int h = t & (HH - 1);
    t >>= 4;
    int s = t & (SS - 1);
    long long b = t >> 11;
    const long long m = b * SS + s;
    const long long src = m * QKVN + h * DHH + 2 * i;
    const long long dst = m * DD + h * DHH + 2 * i;

    float c  = fcos[(long long)s * HALF + i];
    float sn = fsin[(long long)s * HALF + i];

    float xr = __half2float(qkv[src]), xi = __half2float(qkv[src + 1]);
    qb[dst]     = __float2half_rn(xr * c - xi * sn);
    qb[dst + 1] = __float2half_rn(xr * sn + xi * c);
    xr = __half2float(qkv[src + DD]); xi = __half2float(qkv[src + DD + 1]);
    kb[dst]     = __float2half_rn(xr * c - xi * sn);
    kb[dst + 1] = __float2half_rn(xr * sn + xi * c);
}

// v (cols 4096.. of fp16 qkv) -> vt [B,H,DH,S]
__global__ __launch_bounds__(256)
void v_transpose(const h16* __restrict__ qkv, h16* __restrict__ vt)
{
    __shared__ h16 t[32][34];
    const int z = blockIdx.z;
    const int b = z >> 4, h = z & 15;
    const h16* src = qkv + (long long)b * SS * QKVN + 2 * DD + h * DHH;
    h16* dst = vt + (long long)z * DHH * SS;
    const int s0 = blockIdx.x * 32, d0 = blockIdx.y * 32;
    const int tx = threadIdx.x & 31, ty = threadIdx.x >> 5;
#pragma unroll
    for (int i = 0; i < 32; i += 8)
        t[ty + i][tx] = src[(long long)(s0 + ty + i) * QKVN + d0 + tx];
    __syncthreads();
#pragma unroll
    for (int i = 0; i < 32; i += 8)
        dst[(long long)(d0 + ty + i) * SS + s0 + tx] = t[tx][ty + i];
}

// g = silu(f13[:, :FFD]) * f13[:, FFD:]   (fp16 in, fp16 out)
__global__ __launch_bounds__(256)
void silu_h16(const h16* __restrict__ f13, h16* __restrict__ o)
{
    long long i = (long long)blockIdx.x * 256 + threadIdx.x;
    long long m = i / FFD;
    long long j = i - m * FFD;
    const h16* row = f13 + m * F13N;
    float a = __half2float(row[j]);
    float g = (a / (1.0f + __expf(-a))) * __half2float(row[j + FFD]);
    o[i] = __float2half_rn(g);
}

// ------------------------- host ----------------------------------------------
#define GEMM_SMEM (3 * 32768)

static void gemm(const h16* A, const h16* B, const float* Res, float* C, h16* C16,
                 int M, int N, int K,
                 long long lda, long long ldb, long long ldc, long long ldres,
                 float alpha)
{
    dim3 grid(N / 128, M / 128, 1);
    hgemm<<<grid, 256, GEMM_SMEM>>>(A, B, Res, C, C16, M, N, K,
                                    lda, ldb, ldc, ldres, alpha);
}

extern "C" void kernel_launch(void* const* d_in, const int* in_sizes, int n_in,
                              void* d_out, int out_size)
{
    (void)in_sizes; (void)n_in; (void)out_size;
    const float* hidden = (const float*)d_in[0];
    const float* fcos   = (const float*)d_in[1];
    const float* fsin   = (const float*)d_in[2];
    const float* wq     = (const float*)d_in[3];
    const float* wk     = (const float*)d_in[4];
    const float* wv     = (const float*)d_in[5];
    const float* wo     = (const float*)d_in[6];
    const float* w1     = (const float*)d_in[7];
    const float* w2     = (const float*)d_in[8];
    const float* w3     = (const float*)d_in[9];
    const float* anw    = (const float*)d_in[10];
    const float* fnw    = (const float*)d_in[11];
    float* out = (float*)d_out;

    cudaFuncSetAttribute(hgemm, cudaFuncAttributeMaxDynamicSharedMemorySize, GEMM_SMEM);
    cudaFuncSetAttribute(flash_attn, cudaFuncAttributeMaxDynamicSharedMemorySize, FA_SMEM);

    h16 *xb, *wqkvT, *woT, *w13T, *w2T, *qkvh, *qb, *kb, *vt, *attnb, *yb, *f13h, *gb;
    float *h;
    cudaGetSymbolAddress((void**)&xb,    g_xb);
    cudaGetSymbolAddress((void**)&wqkvT, g_wqkvT);
    cudaGetSymbolAddress((void**)&woT,   g_woT);
    cudaGetSymbolAddress((void**)&w13T,  g_w13T);
    cudaGetSymbolAddress((void**)&w2T,   g_w2T);
    cudaGetSymbolAddress((void**)&qkvh,  g_qkvh);
    cudaGetSymbolAddress((void**)&qb,    g_qb);
    cudaGetSymbolAddress((void**)&kb,    g_kb);
    cudaGetSymbolAddress((void**)&vt,    g_vt);
    cudaGetSymbolAddress((void**)&attnb, g_attnb);
    cudaGetSymbolAddress((void**)&h,     g_h);
    cudaGetSymbolAddress((void**)&yb,    g_yb);
    cudaGetSymbolAddress((void**)&f13h,  g_f13h);
    cudaGetSymbolAddress((void**)&gb,    g_gb);

    // weight prep (fp32 -> fp16, transposed to [N,K])
    { dim3 g(DD / 32, DD / 32);
      transpose_h16<<<g, 256>>>(wq, wqkvT,                          DD, DD);
      transpose_h16<<<g, 256>>>(wk, wqkvT + (long long)DD * DD,     DD, DD);
      transpose_h16<<<g, 256>>>(wv, wqkvT + (long long)2 * DD * DD, DD, DD);
      transpose_h16<<<g, 256>>>(wo, woT, DD, DD); }
    { dim3 g(FFD / 32, DD / 32);
      transpose_h16<<<g, 256>>>(w1, w13T, DD, FFD);
      transpose_h16<<<g, 256>>>(w3, w13T + (long long)FFD * DD, DD, FFD); }
    { dim3 g(DD / 32, FFD / 32);
      transpose_h16<<<g, 256>>>(w2, w2T, FFD, DD); }

    // 1. x = rmsnorm(hidden) -> fp16
    rmsnorm_h16<<<MM, 256>>>(hidden, anw, xb);

    // 2. qkv = x @ [wq|wk|wv]  -> fp16
    gemm(xb, wqkvT, nullptr, nullptr, qkvh, MM, QKVN, DD, DD, DD, QKVN, 0, 1.0f);

    // 3. rope + v transpose
    rope_h16<<<(unsigned)((long long)BBATCH * SS * HH * (DHH / 2) / 256), 256>>>(qkvh, fcos, fsin, qb, kb);
    { dim3 g(SS / 32, DHH / 32, BBATCH * HH);
      v_transpose<<<g, 256>>>(qkvh, vt); }

    // 4. fused flash attention -> attnb fp16
    { dim3 g(SS / 128, BBATCH * HH);
      flash_attn<<<g, 256, FA_SMEM>>>(qb, kb, vt, attnb); }

    // 5. h = hidden + attn @ wo
    gemm(attnb, woT, hidden, h, nullptr, MM, DD, DD, DD, DD, DD, DD, 1.0f);

    // 6. y = rmsnorm(h) -> fp16
    rmsnorm_h16<<<MM, 256>>>(h, fnw, yb);

    // 7. f13 = y @ [w1|w3] -> fp16
    gemm(yb, w13T, nullptr, nullptr, f13h, MM, F13N, DD, DD, DD, F13N, 0, 1.0f);

    // 8. g = silu(f1)*f3 -> fp16
    silu_h16<<<(unsigned)((long long)MM * FFD / 256), 256>>>(f13h, gb);

    // 9. out = h + g @ w2
    gemm(gb, w2T, h, out, nullptr, MM, DD, FFD, FFD, FFD, DD, DD, 1.0f);
}

// round 6
// speedup vs baseline: 8.3338x; 1.0786x over previous
#include <cuda_runtime.h>
#include <cuda_fp16.h>
#include <math.h>
#include <stdint.h>

#define BBATCH 2
#define SS 2048
#define DD 2048
#define HH 16
#define DHH 128
#define FFD 5632
#define MM (BBATCH * SS)
#define QKVN (3 * DD)        // 6144
#define F13N (2 * FFD)       // 11264

typedef __half h16;

// ------------------------- scratch (device globals) -------------------------
__device__ h16   g_xb   [(long long)MM * DD];
__device__ h16   g_wqkvT[(long long)QKVN * DD];
__device__ h16   g_woT  [(long long)DD * DD];
__device__ h16   g_w13T [(long long)F13N * DD];   // interleaved: row 2j = w1_j, 2j+1 = w3_j
__device__ h16   g_w2T  [(long long)DD * FFD];
__device__ h16   g_qkvh [(long long)MM * QKVN];
__device__ h16   g_qb   [(long long)MM * DD];
__device__ h16   g_kb   [(long long)MM * DD];
__device__ h16   g_vt   [(long long)BBATCH * HH * DHH * SS];
__device__ h16   g_attnb[(long long)MM * DD];
__device__ float g_h    [(long long)MM * DD];
__device__ h16   g_yb   [(long long)MM * DD];
__device__ h16   g_gb   [(long long)MM * FFD];

// ------------------------- helpers ------------------------------------------
__device__ __forceinline__ uint32_t smem_u32(const void* p) {
    uint32_t a;
    asm("{ .reg .u64 t; cvta.to.shared.u64 t, %1; cvt.u32.u64 %0, t; }" : "=r"(a) : "l"(p));
    return a;
}

__device__ __forceinline__ void cp_async16(uint32_t dst, const void* src) {
    asm volatile("cp.async.cg.shared.global [%0], [%1], 16;" :: "r"(dst), "l"(src));
}
__device__ __forceinline__ void cp_commit() {
    asm volatile("cp.async.commit_group;");
}
__device__ __forceinline__ void cp_wait1() {
    asm volatile("cp.async.wait_group 1;");
}
__device__ __forceinline__ void cp_wait0() {
    asm volatile("cp.async.wait_group 0;");
}

__device__ __forceinline__ void ldmx4(uint32_t* r, uint32_t addr) {
    asm volatile("ldmatrix.sync.aligned.m8n8.x4.shared.b16 {%0,%1,%2,%3}, [%4];"
                 : "=r"(r[0]), "=r"(r[1]), "=r"(r[2]), "=r"(r[3]) : "r"(addr));
}
__device__ __forceinline__ void ldmx2(uint32_t* r, uint32_t addr) {
    asm volatile("ldmatrix.sync.aligned.m8n8.x2.shared.b16 {%0,%1}, [%2];"
                 : "=r"(r[0]), "=r"(r[1]) : "r"(addr));
}
__device__ __forceinline__ void mma16816(float* c, const uint32_t* a, const uint32_t* b) {
    asm volatile(
        "mma.sync.aligned.m16n8k16.row.col.f32.f16.f16.f32 "
        "{%0,%1,%2,%3}, {%4,%5,%6,%7}, {%8,%9}, {%0,%1,%2,%3};"
        : "+f"(c[0]), "+f"(c[1]), "+f"(c[2]), "+f"(c[3])
        : "r"(a[0]), "r"(a[1]), "r"(a[2]), "r"(a[3]), "r"(b[0]), "r"(b[1]));
}
__device__ __forceinline__ uint32_t packh2(float a, float b) {
    __half2 h = __floats2half2_rn(a, b);
    return *reinterpret_cast<uint32_t*>(&h);
}
__device__ __forceinline__ float siluf(float a) {
    return a / (1.0f + __expf(-a));
}

// ------------------------- HGEMM (mma.sync) ----------------------------------
// C[m][n] = alpha * sum_k A[m][k]*B[n][k]. A/B K-major fp16.
// mode 0: fp32 out (+Res), mode 1: fp16 out, mode 2: silu-pair fp16 out
// CTA tile 128x128, BK=64, 3-stage cp.async pipeline, 8 warps (2m x 4n).
__device__ __forceinline__ void stage_load(uint32_t sdst, const h16* g, int row0,
                                           long long ld, int k0, int tid)
{
    const int r = tid >> 1;
    const int cb = (tid & 1) * 4;
    const h16* grow = g + (long long)(row0 + r) * ld + k0;
#pragma unroll
    for (int i = 0; i < 4; i++) {
        int c = cb + i;
        uint32_t dst = sdst + (uint32_t)(r * 128 + ((c ^ (r & 7)) * 16));
        cp_async16(dst, grow + c * 8);
    }
}

__global__ __launch_bounds__(256, 2)
void hgemm(const h16* __restrict__ A, const h16* __restrict__ B,
           const float* __restrict__ Res, float* __restrict__ C,
           h16* __restrict__ C16,
           int M, int N, int K,
           long long lda, long long ldb, long long ldc, long long ldres,
           float alpha, int mode)
{
    extern __shared__ char smem[];

    const int m0 = blockIdx.y * 128;
    const int n0 = blockIdx.x * 128;

    const int tid = threadIdx.x;
    const int lane = tid & 31;
    const int wid = tid >> 5;
    const int wm = wid >> 2;
    const int wn = wid & 3;

    const uint32_t sb = smem_u32(smem);
    const int KT = K >> 6;

    const int nPro = (KT < 2) ? KT : 2;
    for (int s = 0; s < nPro; s++) {
        uint32_t base = sb + (uint32_t)(s % 3) * 32768u;
        stage_load(base, A, m0, lda, s * 64, tid);
        stage_load(base + 16384u, B, n0, ldb, s * 64, tid);
        cp_commit();
    }

    float acc[4][4][4];
#pragma unroll
    for (int i = 0; i < 4; i++)
#pragma unroll
        for (int j = 0; j < 4; j++)
#pragma unroll
            for (int q = 0; q < 4; q++) acc[i][j][q] = 0.0f;

    const int aRow = wm * 64 + (lane & 15);
    const int aKsel = lane >> 4;
    const int aSwz = aRow & 7;
    const int bRowBase = wn * 32 + (lane & 7);
    const int bKsel = (lane >> 3) & 1;

    for (int s = 0; s < KT; s++) {
        cp_wait1();
        __syncthreads();
        if (s + 2 < KT) {
            uint32_t base = sb + (uint32_t)((s + 2) % 3) * 32768u;
            stage_load(base, A, m0, lda, (s + 2) * 64, tid);
            stage_load(base + 16384u, B, n0, ldb, (s + 2) * 64, tid);
        }
        cp_commit();

        const uint32_t base = sb + (uint32_t)(s % 3) * 32768u;
#pragma unroll
        for (int kc = 0; kc < 4; kc++) {
            uint32_t a[4][4], b[4][2];
#pragma unroll
            for (int mt = 0; mt < 4; mt++) {
                uint32_t ad = base + (uint32_t)((aRow + mt * 16) * 128 +
                              (((kc * 2 + aKsel) ^ aSwz) * 16));
                ldmx4(a[mt], ad);
            }
#pragma unroll
            for (int nt = 0; nt < 4; nt++) {
                int nRow = bRowBase + nt * 8;
                uint32_t bd = base + 16384u + (uint32_t)(nRow * 128 +
                              (((kc * 2 + bKsel) ^ (nRow & 7)) * 16));
                ldmx2(b[nt], bd);
            }
#pragma unroll
            for (int mt = 0; mt < 4; mt++)
#pragma unroll
                for (int nt = 0; nt < 4; nt++)
                    mma16816(acc[mt][nt], a[mt], b[nt]);
        }
        __syncthreads();
    }

#pragma unroll
    for (int mt = 0; mt < 4; mt++) {
#pragma unroll
        for (int nt = 0; nt < 4; nt++) {
            const int m = m0 + wm * 64 + mt * 16 + (lane >> 2);
            const int n = n0 + wn * 32 + nt * 8 + (lane & 3) * 2;
            if (mode == 2) {
                // acc cols n (w1_j) and n+1 (w3_j), j = n>>1
                const int j = n >> 1;
                C16[(long long)m * ldc + j] =
                    __float2half_rn(siluf(acc[mt][nt][0]) * acc[mt][nt][1]);
                C16[(long long)(m + 8) * ldc + j] =
                    __float2half_rn(siluf(acc[mt][nt][2]) * acc[mt][nt][3]);
            } else if (mode == 1) {
                uint32_t h0 = packh2(acc[mt][nt][0] * alpha, acc[mt][nt][1] * alpha);
                uint32_t h1 = packh2(acc[mt][nt][2] * alpha, acc[mt][nt][3] * alpha);
                *reinterpret_cast<uint32_t*>(&C16[(long long)m * ldc + n]) = h0;
                *reinterpret_cast<uint32_t*>(&C16[(long long)(m + 8) * ldc + n]) = h1;
            } else {
                float2 v0, v1;
                v0.x = acc[mt][nt][0] * alpha; v0.y = acc[mt][nt][1] * alpha;
                v1.x = acc[mt][nt][2] * alpha; v1.y = acc[mt][nt][3] * alpha;
                if (Res) {
                    float2 r0 = *reinterpret_cast<const float2*>(&Res[(long long)m * ldres + n]);
                    float2 r1 = *reinterpret_cast<const float2*>(&Res[(long long)(m + 8) * ldres + n]);
                    v0.x += r0.x; v0.y += r0.y; v1.x += r1.x; v1.y += r1.y;
                }
                *reinterpret_cast<float2*>(&C[(long long)m * ldc + n]) = v0;
                *reinterpret_cast<float2*>(&C[(long long)(m + 8) * ldc + n]) = v1;
            }
        }
    }
}

// ------------------------- fused flash attention ------------------------------
// Grid: (SS/128, B*H). 8 warps; warp handles 16 query rows.
#define FA_SMEM (32768 + 2 * 65536)
#define SM_SCALE 0.08838834764831845f

__global__ __launch_bounds__(256, 1)
void flash_attn(const h16* __restrict__ qg, const h16* __restrict__ kg,
                const h16* __restrict__ vtg, h16* __restrict__ og)
{
    extern __shared__ char smem[];
    const int qt = (int)(gridDim.x - 1) - (int)blockIdx.x;   // heavy tiles first
    const int bh = blockIdx.y;
    const int b = bh >> 4, h = bh & 15;

    const h16* qp = qg + (long long)b * SS * DD + h * DHH;
    const h16* kp = kg + (long long)b * SS * DD + h * DHH;
    const h16* vp = vtg + (long long)bh * DHH * SS;

    const int tid = threadIdx.x;
    const int lane = tid & 31;
    const int wid = tid >> 5;
    const int wrow = wid * 16;

    const uint32_t sb = smem_u32(smem);
    const uint32_t qbs = sb;

    stage_load(qbs, qp, qt * 128, DD, 0, tid);
    stage_load(qbs + 16384u, qp, qt * 128, DD, 64, tid);
    cp_commit();
    {
        uint32_t kvb = sb + 32768u;
        stage_load(kvb, kp, 0, DD, 0, tid);
        stage_load(kvb + 16384u, kp, 0, DD, 64, tid);
        stage_load(kvb + 32768u, vp, 0, SS, 0, tid);
        stage_load(kvb + 49152u, vp, 0, SS, 64, tid);
        cp_commit();
    }

    const int aRow = wrow + (lane & 15);
    const int aKsel = lane >> 4;
    const int aSwz = aRow & 7;
    const int bRow7 = lane & 7;
    const int bNtSel = (lane >> 4) & 1;
    const int bKsel = (lane >> 3) & 1;

    uint32_t aq[8][4];
    float o[16][4];
    float mrow[2], lrow[2];
#pragma unroll
    for (int i = 0; i < 16; i++)
#pragma unroll
        for (int j = 0; j < 4; j++) o[i][j] = 0.0f;
    mrow[0] = mrow[1] = -1e30f;
    lrow[0] = lrow[1] = 0.0f;

    const int nKT = qt + 1;
    for (int kt = 0; kt < nKT; kt++) {
        cp_wait0();
        __syncthreads();
        const uint32_t kvb = sb + 32768u + (uint32_t)(kt & 1) * 65536u;
        if (kt + 1 < nKT) {
            uint32_t nb = sb + 32768u + (uint32_t)((kt + 1) & 1) * 65536u;
            stage_load(nb, kp, (kt + 1) * 128, DD, 0, tid);
            stage_load(nb + 16384u, kp, (kt + 1) * 128, DD, 64, tid);
            stage_load(nb + 32768u, vp, 0, SS, (kt + 1) * 128, tid);
            stage_load(nb + 49152u, vp, 0, SS, (kt + 1) * 128 + 64, tid);
            cp_commit();
        }
        if (kt == 0) {
#pragma unroll
            for (int kc = 0; kc < 8; kc++) {
                uint32_t base = qbs + (kc >= 4 ? 16384u : 0u);
                uint32_t ad = base + (uint32_t)(aRow * 128 +
                              ((((kc & 3) * 2 + aKsel) ^ aSwz) * 16));
                ldmx4(aq[kc], ad);
            }
        }

        float s[16][4];
#pragma unroll
        for (int i = 0; i < 16; i++)
#pragma unroll
            for (int j = 0; j < 4; j++) s[i][j] = 0.0f;
#pragma unroll
        for (int ntp = 0; ntp < 8; ntp++) {
#pragma unroll
            for (int kc = 0; kc < 8; kc++) {
                uint32_t base = kvb + (kc >= 4 ? 16384u : 0u);
                int nRow = (ntp * 2 + bNtSel) * 8 + bRow7;
                uint32_t bd = base + (uint32_t)(nRow * 128 +
                              ((((kc & 3) * 2 + bKsel) ^ (nRow & 7)) * 16));
                uint32_t bv[4];
                ldmx4(bv, bd);
                mma16816(s[ntp * 2],     aq[kc], bv);
                mma16816(s[ntp * 2 + 1], aq[kc], bv + 2);
            }
        }

        if (kt == qt) {
            const int ii0 = wrow + (lane >> 2);
#pragma unroll
            for (int nt = 0; nt < 16; nt++) {
                int jj = nt * 8 + 2 * (lane & 3);
                if (jj > ii0)      s[nt][0] = -1e30f;
                if (jj + 1 > ii0)  s[nt][1] = -1e30f;
                if (jj > ii0 + 8)     s[nt][2] = -1e30f;
                if (jj + 1 > ii0 + 8) s[nt][3] = -1e30f;
            }
        }

        float mx0 = -1e30f, mx1 = -1e30f;
#pragma unroll
        for (int nt = 0; nt < 16; nt++) {
            mx0 = fmaxf(mx0, fmaxf(s[nt][0], s[nt][1]));
            mx1 = fmaxf(mx1, fmaxf(s[nt][2], s[nt][3]));
        }
        mx0 = fmaxf(mx0, __shfl_xor_sync(0xffffffffu, mx0, 1));
        mx0 = fmaxf(mx0, __shfl_xor_sync(0xffffffffu, mx0, 2));
        mx1 = fmaxf(mx1, __shfl_xor_sync(0xffffffffu, mx1, 1));
        mx1 = fmaxf(mx1, __shfl_xor_sync(0xffffffffu, mx1, 2));
        const float mn0 = fmaxf(mrow[0], mx0);
        const float mn1 = fmaxf(mrow[1], mx1);
        const float f0 = __expf((mrow[0] - mn0) * SM_SCALE);
        const float f1 = __expf((mrow[1] - mn1) * SM_SCALE);
        mrow[0] = mn0; mrow[1] = mn1;
#pragma unroll
        for (int nt = 0; nt < 16; nt++) {
            o[nt][0] *= f0; o[nt][1] *= f0;
            o[nt][2] *= f1; o[nt][3] *= f1;
        }
        float sum0 = 0.0f, sum1 = 0.0f;
#pragma unroll
        for (int nt = 0; nt < 16; nt++) {
            s[nt][0] = __expf((s[nt][0] - mn0) * SM_SCALE);
            s[nt][1] = __expf((s[nt][1] - mn0) * SM_SCALE);
            s[nt][2] = __expf((s[nt][2] - mn1) * SM_SCALE);
            s[nt][3] = __expf((s[nt][3] - mn1) * SM_SCALE);
            sum0 += s[nt][0] + s[nt][1];
            sum1 += s[nt][2] + s[nt][3];
        }
        sum0 += __shfl_xor_sync(0xffffffffu, sum0, 1);
        sum0 += __shfl_xor_sync(0xffffffffu, sum0, 2);
        sum1 += __shfl_xor_sync(0xffffffffu, sum1, 1);
        sum1 += __shfl_xor_sync(0xffffffffu, sum1, 2);
        lrow[0] = lrow[0] * f0 + sum0;
        lrow[1] = lrow[1] * f1 + sum1;

#pragma unroll
        for (int kc = 0; kc < 8; kc++) {
            uint32_t ap[4];
            ap[0] = packh2(s[kc * 2][0], s[kc * 2][1]);
            ap[1] = packh2(s[kc * 2][2], s[kc * 2][3]);
            ap[2] = packh2(s[kc * 2 + 1][0], s[kc * 2 + 1][1]);
            ap[3] = packh2(s[kc * 2 + 1][2], s[kc * 2 + 1][3]);
#pragma unroll
            for (int ntp = 0; ntp < 8; ntp++) {
                uint32_t base = kvb + 32768u + (kc >= 4 ? 16384u : 0u);
                int nRow = (ntp * 2 + bNtSel) * 8 + bRow7;
                uint32_t bd = base + (uint32_t)(nRow * 128 +
                              ((((kc & 3) * 2 + bKsel) ^ (nRow & 7)) * 16));
                uint32_t bv[4];
                ldmx4(bv, bd);
                mma16816(o[ntp * 2],     ap, bv);
                mma16816(o[ntp * 2 + 1], ap, bv + 2);
            }
        }
    }

    const float inv0 = 1.0f / lrow[0];
    const float inv1 = 1.0f / lrow[1];
    const long long row0 = (long long)b * SS + qt * 128 + wrow + (lane >> 2);
#pragma unroll
    for (int nt = 0; nt < 16; nt++) {
        int dcol = h * DHH + nt * 8 + 2 * (lane & 3);
        uint32_t h0 = packh2(o[nt][0] * inv0, o[nt][1] * inv0);
        uint32_t h1 = packh2(o[nt][2] * inv1, o[nt][3] * inv1);
        *reinterpret_cast<uint32_t*>(&og[row0 * DD + dcol]) = h0;
        *reinterpret_cast<uint32_t*>(&og[(row0 + 8) * DD + dcol]) = h1;
    }
}

// ------------------------- elementwise kernels --------------------------------
__global__ __launch_bounds__(256)
void rmsnorm_h16(const float* __restrict__ in, const float* __restrict__ w,
                 h16* __restrict__ o)
{
    __shared__ float red[256];
    const long long row = blockIdx.x;
    const float* p = in + row * DD;
    const int tid = threadIdx.x;
    float v[8];
    float ss = 0.0f;
#pragma unroll
    for (int t = 0; t < 8; t++) { v[t] = p[tid + t * 256]; ss += v[t] * v[t]; }
    red[tid] = ss;
    __syncthreads();
    for (int s = 128; s > 0; s >>= 1) {
        if (tid < s) red[tid] += red[tid + s];
        __syncthreads();
    }
    const float scale = rsqrtf(red[0] / (float)DD + 1e-6f);
#pragma unroll
    for (int t = 0; t < 8; t++) {
        int j = tid + t * 256;
        o[row * DD + j] = __float2half_rn(v[t] * scale * w[j]);
    }
}

// W [K,N] fp32 -> WT row (n*rowMul + rowOff) of [*, K] fp16
__global__ __launch_bounds__(256)
void transpose_h16(const float* __restrict__ W, h16* __restrict__ out, int K, int N,
                   int rowMul, int rowOff)
{
    __shared__ float t[32][33];
    const int k0 = blockIdx.y * 32, n0 = blockIdx.x * 32;
    const int tx = threadIdx.x & 31, ty = threadIdx.x >> 5;
#pragma unroll
    for (int i = 0; i < 32; i += 8)
        t[ty + i][tx] = W[(long long)(k0 + ty + i) * N + n0 + tx];
    __syncthreads();
#pragma unroll
    for (int i = 0; i < 32; i += 8)
        out[(long long)((n0 + ty + i) * rowMul + rowOff) * K + k0 + tx] =
            __float2half_rn(t[tx][ty + i]);
}

__global__ __launch_bounds__(256)
void rope_h16(const h16* __restrict__ qkv,
              const float* __restrict__ fcos, const float* __restrict__ fsin,
              h16* __restrict__ qb, h16* __restrict__ kb)
{
    long long idx = (long long)blockIdx.x * 256 + threadIdx.x;
    const int HALF = DHH / 2;
    int i = idx & (HALF - 1);
    long long t = idx >> 6;
    int h = t & (HH - 1);
    t >>= 4;
    int s = t & (SS - 1);
    long long b = t >> 11;
    const long long m = b * SS + s;
    const long long src = m * QKVN + h * DHH + 2 * i;
    const long long dst = m * DD + h * DHH + 2 * i;

    float c  = fcos[(long long)s * HALF + i];
    float sn = fsin[(long long)s * HALF + i];

    float xr = __half2float(qkv[src]), xi = __half2float(qkv[src + 1]);
    qb[dst]     = __float2half_rn(xr * c - xi * sn);
    qb[dst + 1] = __float2half_rn(xr * sn + xi * c);
    xr = __half2float(qkv[src + DD]); xi = __half2float(qkv[src + DD + 1]);
    kb[dst]     = __float2half_rn(xr * c - xi * sn);
    kb[dst + 1] = __float2half_rn(xr * sn + xi * c);
}

__global__ __launch_bounds__(256)
void v_transpose(const h16* __restrict__ qkv, h16* __restrict__ vt)
{
    __shared__ h16 t[32][34];
    const int z = blockIdx.z;
    const int b = z >> 4, h = z & 15;
    const h16* src = qkv + (long long)b * SS * QKVN + 2 * DD + h * DHH;
    h16* dst = vt + (long long)z * DHH * SS;
    const int s0 = blockIdx.x * 32, d0 = blockIdx.y * 32;
    const int tx = threadIdx.x & 31, ty = threadIdx.x >> 5;
#pragma unroll
    for (int i = 0; i < 32; i += 8)
        t[ty + i][tx] = src[(long long)(s0 + ty + i) * QKVN + d0 + tx];
    __syncthreads();
#pragma unroll
    for (int i = 0; i < 32; i += 8)
        dst[(long long)(d0 + ty + i) * SS + s0 + tx] = t[tx][ty + i];
}

// ------------------------- host ----------------------------------------------
#define GEMM_SMEM (3 * 32768)

static void gemm(const h16* A, const h16* B, const float* Res, float* C, h16* C16,
                 int M, int N, int K,
                 long long lda, long long ldb, long long ldc, long long ldres,
                 float alpha, int mode, cudaStream_t st)
{
    dim3 grid(N / 128, M / 128, 1);
    hgemm<<<grid, 256, GEMM_SMEM, st>>>(A, B, Res, C, C16, M, N, K,
                                        lda, ldb, ldc, ldres, alpha, mode);
}

extern "C" void kernel_launch(void* const* d_in, const int* in_sizes, int n_in,
                              void* d_out, int out_size)
{
    (void)in_sizes; (void)n_in; (void)out_size;
    const float* hidden = (const float*)d_in[0];
    const float* fcos   = (const float*)d_in[1];
    const float* fsin   = (const float*)d_in[2];
    const float* wq     = (const float*)d_in[3];
    const float* wk     = (const float*)d_in[4];
    const float* wv     = (const float*)d_in[5];
    const float* wo     = (const float*)d_in[6];
    const float* w1     = (const float*)d_in[7];
    const float* w2     = (const float*)d_in[8];
    const float* w3     = (const float*)d_in[9];
    const float* anw    = (const float*)d_in[10];
    const float* fnw    = (const float*)d_in[11];
    float* out = (float*)d_out;

    static cudaStream_t s2 = nullptr;
    static cudaEvent_t evF = nullptr, evA = nullptr, evB = nullptr;
    if (s2 == nullptr) {
        cudaStreamCreateWithFlags(&s2, cudaStreamNonBlocking);
        cudaEventCreateWithFlags(&evF, cudaEventDisableTiming);
        cudaEventCreateWithFlags(&evA, cudaEventDisableTiming);
        cudaEventCreateWithFlags(&evB, cudaEventDisableTiming);
    }

    cudaFuncSetAttribute(hgemm, cudaFuncAttributeMaxDynamicSharedMemorySize, GEMM_SMEM);
    cudaFuncSetAttribute(flash_attn, cudaFuncAttributeMaxDynamicSharedMemorySize, FA_SMEM);

    h16 *xb, *wqkvT, *woT, *w13T, *w2T, *qkvh, *qb, *kb, *vt, *attnb, *yb, *gb;
    float *h;
    cudaGetSymbolAddress((void**)&xb,    g_xb);
    cudaGetSymbolAddress((void**)&wqkvT, g_wqkvT);
    cudaGetSymbolAddress((void**)&woT,   g_woT);
    cudaGetSymbolAddress((void**)&w13T,  g_w13T);
    cudaGetSymbolAddress((void**)&w2T,   g_w2T);
    cudaGetSymbolAddress((void**)&qkvh,  g_qkvh);
    cudaGetSymbolAddress((void**)&qb,    g_qb);
    cudaGetSymbolAddress((void**)&kb,    g_kb);
    cudaGetSymbolAddress((void**)&vt,    g_vt);
    cudaGetSymbolAddress((void**)&attnb, g_attnb);
    cudaGetSymbolAddress((void**)&h,     g_h);
    cudaGetSymbolAddress((void**)&yb,    g_yb);
    cudaGetSymbolAddress((void**)&gb,    g_gb);

    // ---- fork side stream for weight prep
    cudaEventRecord(evF, 0);
    cudaStreamWaitEvent(s2, evF, 0);

    { dim3 g(DD / 32, DD / 32);
      transpose_h16<<<g, 256, 0, s2>>>(wq, wqkvT,                          DD, DD, 1, 0);
      transpose_h16<<<g, 256, 0, s2>>>(wk, wqkvT + (long long)DD * DD,     DD, DD, 1, 0);
      transpose_h16<<<g, 256, 0, s2>>>(wv, wqkvT + (long long)2 * DD * DD, DD, DD, 1, 0); }
    cudaEventRecord(evA, s2);
    { dim3 g(DD / 32, DD / 32);
      transpose_h16<<<g, 256, 0, s2>>>(wo, woT, DD, DD, 1, 0); }
    { dim3 g(FFD / 32, DD / 32);
      transpose_h16<<<g, 256, 0, s2>>>(w1, w13T, DD, FFD, 2, 0);   // even rows
      transpose_h16<<<g, 256, 0, s2>>>(w3, w13T, DD, FFD, 2, 1); } // odd rows
    { dim3 g(DD / 32, FFD / 32);
      transpose_h16<<<g, 256, 0, s2>>>(w2, w2T, FFD, DD, 1, 0); }
    cudaEventRecord(evB, s2);

    // ---- main chain (default stream)
    // 1. x = rmsnorm(hidden) -> fp16
    rmsnorm_h16<<<MM, 256>>>(hidden, anw, xb);

    cudaStreamWaitEvent(0, evA, 0);
    // 2. qkv = x @ [wq|wk|wv] -> fp16
    gemm(xb, wqkvT, nullptr, nullptr, qkvh, MM, QKVN, DD, DD, DD, QKVN, 0, 1.0f, 1, 0);

    // 3. rope + v transpose
    rope_h16<<<(unsigned)((long long)BBATCH * SS * HH * (DHH / 2) / 256), 256>>>(qkvh, fcos, fsin, qb, kb);
    { dim3 g(SS / 32, DHH / 32, BBATCH * HH);
      v_transpose<<<g, 256>>>(qkvh, vt); }

    // 4. fused flash attention -> attnb fp16
    { dim3 g(SS / 128, BBATCH * HH);
      flash_attn<<<g, 256, FA_SMEM>>>(qb, kb, vt, attnb); }

    cudaStreamWaitEvent(0, evB, 0);
    // 5. h = hidden + attn @ wo
    gemm(attnb, woT, hidden, h, nullptr, MM, DD, DD, DD, DD, DD, DD, 1.0f, 0, 0);

    // 6. y = rmsnorm(h) -> fp16
    rmsnorm_h16<<<MM, 256>>>(h, fnw, yb);

    // 7+8. g = silu(y@w1) * (y@w3) -> fp16 (fused epilogue, interleaved weights)
    gemm(yb, w13T, nullptr, nullptr, gb, MM, F13N, DD, DD, DD, FFD, 0, 1.0f, 2, 0);

    // 9. out = h + g @ w2
    gemm(gb, w2T, h, out, nullptr, MM, DD, FFD, FFD, FFD, DD, DD, 1.0f, 0, 0);
}

// round 7
// speedup vs baseline: 8.4266x; 1.0111x over previous
#include <cuda_runtime.h>
#include <cuda_fp16.h>
#include <math.h>
#include <stdint.h>

#define BBATCH 2
#define SS 2048
#define DD 2048
#define HH 16
#define DHH 128
#define FFD 5632
#define MM (BBATCH * SS)
#define QKVN (3 * DD)        // 6144
#define F13N (2 * FFD)       // 11264

typedef __half h16;

// ------------------------- scratch (device globals) -------------------------
__device__ h16   g_xb   [(long long)MM * DD];
__device__ h16   g_wqkvT[(long long)QKVN * DD];
__device__ h16   g_woT  [(long long)DD * DD];
__device__ h16   g_w13T [(long long)F13N * DD];   // interleaved: row 2j = w1_j, 2j+1 = w3_j
__device__ h16   g_w2T  [(long long)DD * FFD];
__device__ h16   g_qb   [(long long)MM * DD];
__device__ h16   g_kb   [(long long)MM * DD];
__device__ h16   g_vb   [(long long)MM * DD];
__device__ h16   g_attnb[(long long)MM * DD];
__device__ float g_h    [(long long)MM * DD];
__device__ h16   g_yb   [(long long)MM * DD];
__device__ h16   g_gb   [(long long)MM * FFD];

// ------------------------- helpers ------------------------------------------
__device__ __forceinline__ uint32_t smem_u32(const void* p) {
    uint32_t a;
    asm("{ .reg .u64 t; cvta.to.shared.u64 t, %1; cvt.u32.u64 %0, t; }" : "=r"(a) : "l"(p));
    return a;
}

__device__ __forceinline__ void cp_async16(uint32_t dst, const void* src) {
    asm volatile("cp.async.cg.shared.global [%0], [%1], 16;" :: "r"(dst), "l"(src));
}
__device__ __forceinline__ void cp_commit() {
    asm volatile("cp.async.commit_group;");
}
__device__ __forceinline__ void cp_wait1() {
    asm volatile("cp.async.wait_group 1;");
}
__device__ __forceinline__ void cp_wait0() {
    asm volatile("cp.async.wait_group 0;");
}

__device__ __forceinline__ void ldmx4(uint32_t* r, uint32_t addr) {
    asm volatile("ldmatrix.sync.aligned.m8n8.x4.shared.b16 {%0,%1,%2,%3}, [%4];"
                 : "=r"(r[0]), "=r"(r[1]), "=r"(r[2]), "=r"(r[3]) : "r"(addr));
}
__device__ __forceinline__ void ldmx4t(uint32_t* r, uint32_t addr) {
    asm volatile("ldmatrix.sync.aligned.m8n8.x4.trans.shared.b16 {%0,%1,%2,%3}, [%4];"
                 : "=r"(r[0]), "=r"(r[1]), "=r"(r[2]), "=r"(r[3]) : "r"(addr));
}
__device__ __forceinline__ void ldmx2(uint32_t* r, uint32_t addr) {
    asm volatile("ldmatrix.sync.aligned.m8n8.x2.shared.b16 {%0,%1}, [%2];"
                 : "=r"(r[0]), "=r"(r[1]) : "r"(addr));
}
__device__ __forceinline__ void mma16816(float* c, const uint32_t* a, const uint32_t* b) {
    asm volatile(
        "mma.sync.aligned.m16n8k16.row.col.f32.f16.f16.f32 "
        "{%0,%1,%2,%3}, {%4,%5,%6,%7}, {%8,%9}, {%0,%1,%2,%3};"
        : "+f"(c[0]), "+f"(c[1]), "+f"(c[2]), "+f"(c[3])
        : "r"(a[0]), "r"(a[1]), "r"(a[2]), "r"(a[3]), "r"(b[0]), "r"(b[1]));
}
__device__ __forceinline__ uint32_t packh2(float a, float b) {
    __half2 h = __floats2half2_rn(a, b);
    return *reinterpret_cast<uint32_t*>(&h);
}
__device__ __forceinline__ float siluf(float a) {
    return a / (1.0f + __expf(-a));
}

// ------------------------- HGEMM (mma.sync) ----------------------------------
// C[m][n] = alpha * sum_k A[m][k]*B[n][k]. A/B K-major fp16.
// mode 0: fp32 out (+Res); mode 1: fp16 out; mode 2: silu-pair fp16 out;
// mode 3: QKV epilogue (rope on q/k to C16/O2, v plain to O3; ldc = DD)
__device__ __forceinline__ void stage_load(uint32_t sdst, const h16* g, int row0,
                                           long long ld, int k0, int tid)
{
    const int r = tid >> 1;
    const int cb = (tid & 1) * 4;
    const h16* grow = g + (long long)(row0 + r) * ld + k0;
#pragma unroll
    for (int i = 0; i < 4; i++) {
        int c = cb + i;
        uint32_t dst = sdst + (uint32_t)(r * 128 + ((c ^ (r & 7)) * 16));
        cp_async16(dst, grow + c * 8);
    }
}

__global__ __launch_bounds__(256, 2)
void hgemm(const h16* __restrict__ A, const h16* __restrict__ B,
           const float* __restrict__ Res, float* __restrict__ C,
           h16* __restrict__ C16, h16* __restrict__ O2, h16* __restrict__ O3,
           const float* __restrict__ FC, const float* __restrict__ FS,
           int M, int N, int K,
           long long lda, long long ldb, long long ldc, long long ldres,
           float alpha, int mode)
{
    extern __shared__ char smem[];

    const int m0 = blockIdx.y * 128;
    const int n0 = blockIdx.x * 128;

    const int tid = threadIdx.x;
    const int lane = tid & 31;
    const int wid = tid >> 5;
    const int wm = wid >> 2;
    const int wn = wid & 3;

    const uint32_t sb = smem_u32(smem);
    const int KT = K >> 6;

    const int nPro = (KT < 2) ? KT : 2;
    for (int s = 0; s < nPro; s++) {
        uint32_t base = sb + (uint32_t)(s % 3) * 32768u;
        stage_load(base, A, m0, lda, s * 64, tid);
        stage_load(base + 16384u, B, n0, ldb, s * 64, tid);
        cp_commit();
    }

    float acc[4][4][4];
#pragma unroll
    for (int i = 0; i < 4; i++)
#pragma unroll
        for (int j = 0; j < 4; j++)
#pragma unroll
            for (int q = 0; q < 4; q++) acc[i][j][q] = 0.0f;

    const int aRow = wm * 64 + (lane & 15);
    const int aKsel = lane >> 4;
    const int aSwz = aRow & 7;
    const int bRowBase = wn * 32 + (lane & 7);
    const int bKsel = (lane >> 3) & 1;

    for (int s = 0; s < KT; s++) {
        cp_wait1();
        __syncthreads();
        if (s + 2 < KT) {
            uint32_t base = sb + (uint32_t)((s + 2) % 3) * 32768u;
            stage_load(base, A, m0, lda, (s + 2) * 64, tid);
            stage_load(base + 16384u, B, n0, ldb, (s + 2) * 64, tid);
        }
        cp_commit();

        const uint32_t base = sb + (uint32_t)(s % 3) * 32768u;
#pragma unroll
        for (int kc = 0; kc < 4; kc++) {
            uint32_t a[4][4], b[4][2];
#pragma unroll
            for (int mt = 0; mt < 4; mt++) {
                uint32_t ad = base + (uint32_t)((aRow + mt * 16) * 128 +
                              (((kc * 2 + aKsel) ^ aSwz) * 16));
                ldmx4(a[mt], ad);
            }
#pragma unroll
            for (int nt = 0; nt < 4; nt++) {
                int nRow = bRowBase + nt * 8;
                uint32_t bd = base + 16384u + (uint32_t)(nRow * 128 +
                              (((kc * 2 + bKsel) ^ (nRow & 7)) * 16));
                ldmx2(b[nt], bd);
            }
#pragma unroll
            for (int mt = 0; mt < 4; mt++)
#pragma unroll
                for (int nt = 0; nt < 4; nt++)
                    mma16816(acc[mt][nt], a[mt], b[nt]);
        }
        __syncthreads();
    }

#pragma unroll
    for (int mt = 0; mt < 4; mt++) {
#pragma unroll
        for (int nt = 0; nt < 4; nt++) {
            const int m = m0 + wm * 64 + mt * 16 + (lane >> 2);
            const int n = n0 + wn * 32 + nt * 8 + (lane & 3) * 2;
            if (mode == 3) {
                const int i = (n & 127) >> 1;
                if (n < 2 * DD) {
                    h16* dst = (n < DD) ? C16 : O2;
                    const int ncol = n & (DD - 1);
                    const int s1 = m & (SS - 1);
                    const int s2 = (m + 8) & (SS - 1);
                    const float c1 = FC[s1 * 64 + i], sn1 = FS[s1 * 64 + i];
                    const float c2 = FC[s2 * 64 + i], sn2 = FS[s2 * 64 + i];
                    uint32_t h0 = packh2(acc[mt][nt][0] * c1 - acc[mt][nt][1] * sn1,
                                         acc[mt][nt][0] * sn1 + acc[mt][nt][1] * c1);
                    uint32_t h1 = packh2(acc[mt][nt][2] * c2 - acc[mt][nt][3] * sn2,
                                         acc[mt][nt][2] * sn2 + acc[mt][nt][3] * c2);
                    *reinterpret_cast<uint32_t*>(&dst[(long long)m * DD + ncol]) = h0;
                    *reinterpret_cast<uint32_t*>(&dst[(long long)(m + 8) * DD + ncol]) = h1;
                } else {
                    const int ncol = n - 2 * DD;
                    uint32_t h0 = packh2(acc[mt][nt][0], acc[mt][nt][1]);
                    uint32_t h1 = packh2(acc[mt][nt][2], acc[mt][nt][3]);
                    *reinterpret_cast<uint32_t*>(&O3[(long long)m * DD + ncol]) = h0;
                    *reinterpret_cast<uint32_t*>(&O3[(long long)(m + 8) * DD + ncol]) = h1;
                }
            } else if (mode == 2) {
                const int j = n >> 1;
                C16[(long long)m * ldc + j] =
                    __float2half_rn(siluf(acc[mt][nt][0]) * acc[mt][nt][1]);
                C16[(long long)(m + 8) * ldc + j] =
                    __float2half_rn(siluf(acc[mt][nt][2]) * acc[mt][nt][3]);
            } else if (mode == 1) {
                uint32_t h0 = packh2(acc[mt][nt][0] * alpha, acc[mt][nt][1] * alpha);
                uint32_t h1 = packh2(acc[mt][nt][2] * alpha, acc[mt][nt][3] * alpha);
                *reinterpret_cast<uint32_t*>(&C16[(long long)m * ldc + n]) = h0;
                *reinterpret_cast<uint32_t*>(&C16[(long long)(m + 8) * ldc + n]) = h1;
            } else {
                float2 v0, v1;
                v0.x = acc[mt][nt][0] * alpha; v0.y = acc[mt][nt][1] * alpha;
                v1.x = acc[mt][nt][2] * alpha; v1.y = acc[mt][nt][3] * alpha;
                if (Res) {
                    float2 r0 = *reinterpret_cast<const float2*>(&Res[(long long)m * ldres + n]);
                    float2 r1 = *reinterpret_cast<const float2*>(&Res[(long long)(m + 8) * ldres + n]);
                    v0.x += r0.x; v0.y += r0.y; v1.x += r1.x; v1.y += r1.y;
                }
                *reinterpret_cast<float2*>(&C[(long long)m * ldc + n]) = v0;
                *reinterpret_cast<float2*>(&C[(long long)(m + 8) * ldc + n]) = v1;
            }
        }
    }
}

// ------------------------- fused flash attention ------------------------------
// Grid: (SS/128, B*H). 8 warps; warp handles 16 query rows.
// V kept in natural [keys][dh] layout; PV B fragments via ldmatrix.trans.
#define FA_SMEM (32768 + 2 * 65536)
#define SM_SCALE 0.08838834764831845f

__global__ __launch_bounds__(256, 1)
void flash_attn(const h16* __restrict__ qg, const h16* __restrict__ kg,
                const h16* __restrict__ vg, h16* __restrict__ og)
{
    extern __shared__ char smem[];
    const int qt = (int)(gridDim.x - 1) - (int)blockIdx.x;   // heavy tiles first
    const int bh = blockIdx.y;
    const int b = bh >> 4, h = bh & 15;

    const h16* qp = qg + (long long)b * SS * DD + h * DHH;
    const h16* kp = kg + (long long)b * SS * DD + h * DHH;
    const h16* vp = vg + (long long)b * SS * DD + h * DHH;

    const int tid = threadIdx.x;
    const int lane = tid & 31;
    const int wid = tid >> 5;
    const int wrow = wid * 16;

    const uint32_t sb = smem_u32(smem);
    const uint32_t qbs = sb;

    stage_load(qbs, qp, qt * 128, DD, 0, tid);
    stage_load(qbs + 16384u, qp, qt * 128, DD, 64, tid);
    cp_commit();
    {
        uint32_t kvb = sb + 32768u;
        stage_load(kvb, kp, 0, DD, 0, tid);
        stage_load(kvb + 16384u, kp, 0, DD, 64, tid);
        stage_load(kvb + 32768u, vp, 0, DD, 0, tid);
        stage_load(kvb + 49152u, vp, 0, DD, 64, tid);
        cp_commit();
    }

    const int aRow = wrow + (lane & 15);
    const int aKsel = lane >> 4;
    const int aSwz = aRow & 7;
    const int bRow7 = lane & 7;
    const int bNtSel = (lane >> 4) & 1;
    const int bKsel = (lane >> 3) & 1;
    // trans-V addressing
    const int kvRowBase = (lane & 7) + ((lane >> 3) & 1) * 8;   // + kc*16
    const int dSel = (lane >> 4) ? 8 : 0;

    uint32_t aq[8][4];
    float o[16][4];
    float mrow[2], lrow[2];
#pragma unroll
    for (int i = 0; i < 16; i++)
#pragma unroll
        for (int j = 0; j < 4; j++) o[i][j] = 0.0f;
    mrow[0] = mrow[1] = -1e30f;
    lrow[0] = lrow[1] = 0.0f;

    const int nKT = qt + 1;
    for (int kt = 0; kt < nKT; kt++) {
        cp_wait0();
        __syncthreads();
        const uint32_t kvb = sb + 32768u + (uint32_t)(kt & 1) * 65536u;
        if (kt + 1 < nKT) {
            uint32_t nb = sb + 32768u + (uint32_t)((kt + 1) & 1) * 65536u;
            stage_load(nb, kp, (kt + 1) * 128, DD, 0, tid);
            stage_load(nb + 16384u, kp, (kt + 1) * 128, DD, 64, tid);
            stage_load(nb + 32768u, vp, (kt + 1) * 128, DD, 0, tid);
            stage_load(nb + 49152u, vp, (kt + 1) * 128, DD, 64, tid);
            cp_commit();
        }
        if (kt == 0) {
#pragma unroll
            for (int kc = 0; kc < 8; kc++) {
                uint32_t base = qbs + (kc >= 4 ? 16384u : 0u);
                uint32_t ad = base + (uint32_t)(aRow * 128 +
                              ((((kc & 3) * 2 + aKsel) ^ aSwz) * 16));
                ldmx4(aq[kc], ad);
            }
        }

        float s[16][4];
#pragma unroll
        for (int i = 0; i < 16; i++)
#pragma unroll
            for (int j = 0; j < 4; j++) s[i][j] = 0.0f;
#pragma unroll
        for (int ntp = 0; ntp < 8; ntp++) {
#pragma unroll
            for (int kc = 0; kc < 8; kc++) {
                uint32_t base = kvb + (kc >= 4 ? 16384u : 0u);
                int nRow = (ntp * 2 + bNtSel) * 8 + bRow7;
                uint32_t bd = base + (uint32_t)(nRow * 128 +
                              ((((kc & 3) * 2 + bKsel) ^ (nRow & 7)) * 16));
                uint32_t bv[4];
                ldmx4(bv, bd);
                mma16816(s[ntp * 2],     aq[kc], bv);
                mma16816(s[ntp * 2 + 1], aq[kc], bv + 2);
            }
        }

        if (kt == qt) {
            const int ii0 = wrow + (lane >> 2);
#pragma unroll
            for (int nt = 0; nt < 16; nt++) {
                int jj = nt * 8 + 2 * (lane & 3);
                if (jj > ii0)      s[nt][0] = -1e30f;
                if (jj + 1 > ii0)  s[nt][1] = -1e30f;
                if (jj > ii0 + 8)     s[nt][2] = -1e30f;
                if (jj + 1 > ii0 + 8) s[nt][3] = -1e30f;
            }
        }

        float mx0 = -1e30f, mx1 = -1e30f;
#pragma unroll
        for (int nt = 0; nt < 16; nt++) {
            mx0 = fmaxf(mx0, fmaxf(s[nt][0], s[nt][1]));
            mx1 = fmaxf(mx1, fmaxf(s[nt][2], s[nt][3]));
        }
        mx0 = fmaxf(mx0, __shfl_xor_sync(0xffffffffu, mx0, 1));
        mx0 = fmaxf(mx0, __shfl_xor_sync(0xffffffffu, mx0, 2));
        mx1 = fmaxf(mx1, __shfl_xor_sync(0xffffffffu, mx1, 1));
        mx1 = fmaxf(mx1, __shfl_xor_sync(0xffffffffu, mx1, 2));
        const float mn0 = fmaxf(mrow[0], mx0);
        const float mn1 = fmaxf(mrow[1], mx1);
        const float f0 = __expf((mrow[0] - mn0) * SM_SCALE);
        const float f1 = __expf((mrow[1] - mn1) * SM_SCALE);
        mrow[0] = mn0; mrow[1] = mn1;
#pragma unroll
        for (int nt = 0; nt < 16; nt++) {
            o[nt][0] *= f0; o[nt][1] *= f0;
            o[nt][2] *= f1; o[nt][3] *= f1;
        }
        float sum0 = 0.0f, sum1 = 0.0f;
#pragma unroll
        for (int nt = 0; nt < 16; nt++) {
            s[nt][0] = __expf((s[nt][0] - mn0) * SM_SCALE);
            s[nt][1] = __expf((s[nt][1] - mn0) * SM_SCALE);
            s[nt][2] = __expf((s[nt][2] - mn1) * SM_SCALE);
            s[nt][3] = __expf((s[nt][3] - mn1) * SM_SCALE);
            sum0 += s[nt][0] + s[nt][1];
            sum1 += s[nt][2] + s[nt][3];
        }
        sum0 += __shfl_xor_sync(0xffffffffu, sum0, 1);
        sum0 += __shfl_xor_sync(0xffffffffu, sum0, 2);
        sum1 += __shfl_xor_sync(0xffffffffu, sum1, 1);
        sum1 += __shfl_xor_sync(0xffffffffu, sum1, 2);
        lrow[0] = lrow[0] * f0 + sum0;
        lrow[1] = lrow[1] * f1 + sum1;

        // O += P V ; V natural layout, B fragments via ldmatrix.trans
#pragma unroll
        for (int kc = 0; kc < 8; kc++) {
            uint32_t ap[4];
            ap[0] = packh2(s[kc * 2][0], s[kc * 2][1]);
            ap[1] = packh2(s[kc * 2][2], s[kc * 2][3]);
            ap[2] = packh2(s[kc * 2 + 1][0], s[kc * 2 + 1][1]);
            ap[3] = packh2(s[kc * 2 + 1][2], s[kc * 2 + 1][3]);
            const int kvRow = kc * 16 + kvRowBase;
            const uint32_t rowBase = kvb + 32768u + (uint32_t)(kvRow * 128);
            const uint32_t swz = (uint32_t)(kvRow & 7);
#pragma unroll
            for (int ntp = 0; ntp < 8; ntp++) {
                const int d0 = ntp * 16;
                const uint32_t sub = (d0 >= 64) ? 16384u : 0u;
                const int c8 = ((d0 & 63) + dSel) >> 3;
                uint32_t bd = rowBase + sub + (uint32_t)(((uint32_t)c8 ^ swz) * 16);
                uint32_t bv[4];
                ldmx4t(bv, bd);
                mma16816(o[ntp * 2],     ap, bv);
                mma16816(o[ntp * 2 + 1], ap, bv + 2);
            }
        }
    }

    const float inv0 = 1.0f / lrow[0];
    const float inv1 = 1.0f / lrow[1];
    const long long row0 = (long long)b * SS + qt * 128 + wrow + (lane >> 2);
#pragma unroll
    for (int nt = 0; nt < 16; nt++) {
        int dcol = h * DHH + nt * 8 + 2 * (lane & 3);
        uint32_t h0 = packh2(o[nt][0] * inv0, o[nt][1] * inv0);
        uint32_t h1 = packh2(o[nt][2] * inv1, o[nt][3] * inv1);
        *reinterpret_cast<uint32_t*>(&og[row0 * DD + dcol]) = h0;
        *reinterpret_cast<uint32_t*>(&og[(row0 + 8) * DD + dcol]) = h1;
    }
}

// ------------------------- elementwise kernels --------------------------------
__global__ __launch_bounds__(256)
void rmsnorm_h16(const float* __restrict__ in, const float* __restrict__ w,
                 h16* __restrict__ o)
{
    __shared__ float red[256];
    const long long row = blockIdx.x;
    const float* p = in + row * DD;
    const int tid = threadIdx.x;
    float v[8];
    float ss = 0.0f;
#pragma unroll
    for (int t = 0; t < 8; t++) { v[t] = p[tid + t * 256]; ss += v[t] * v[t]; }
    red[tid] = ss;
    __syncthreads();
    for (int s = 128; s > 0; s >>= 1) {
        if (tid < s) red[tid] += red[tid + s];
        __syncthreads();
    }
    const float scale = rsqrtf(red[0] / (float)DD + 1e-6f);
#pragma unroll
    for (int t = 0; t < 8; t++) {
        int j = tid + t * 256;
        o[row * DD + j] = __float2half_rn(v[t] * scale * w[j]);
    }
}

// W [K,N] fp32 -> WT row (n*rowMul + rowOff) of [*, K] fp16
__global__ __launch_bounds__(256)
void transpose_h16(const float* __restrict__ W, h16* __restrict__ out, int K, int N,
                   int rowMul, int rowOff)
{
    __shared__ float t[32][33];
    const int k0 = blockIdx.y * 32, n0 = blockIdx.x * 32;
    const int tx = threadIdx.x & 31, ty = threadIdx.x >> 5;
#pragma unroll
    for (int i = 0; i < 32; i += 8)
        t[ty + i][tx] = W[(long long)(k0 + ty + i) * N + n0 + tx];
    __syncthreads();
#pragma unroll
    for (int i = 0; i < 32; i += 8)
        out[(long long)((n0 + ty + i) * rowMul + rowOff) * K + k0 + tx] =
            __float2half_rn(t[tx][ty + i]);
}

// ------------------------- host ----------------------------------------------
#define GEMM_SMEM (3 * 32768)

static void gemm(const h16* A, const h16* B, const float* Res, float* C,
                 h16* C16, h16* O2, h16* O3, const float* FC, const float* FS,
                 int M, int N, int K,
                 long long lda, long long ldb, long long ldc, long long ldres,
                 float alpha, int mode, cudaStream_t st)
{
    dim3 grid(N / 128, M / 128, 1);
    hgemm<<<grid, 256, GEMM_SMEM, st>>>(A, B, Res, C, C16, O2, O3, FC, FS,
                                        M, N, K, lda, ldb, ldc, ldres, alpha, mode);
}

extern "C" void kernel_launch(void* const* d_in, const int* in_sizes, int n_in,
                              void* d_out, int out_size)
{
    (void)in_sizes; (void)n_in; (void)out_size;
    const float* hidden = (const float*)d_in[0];
    const float* fcos   = (const float*)d_in[1];
    const float* fsin   = (const float*)d_in[2];
    const float* wq     = (const float*)d_in[3];
    const float* wk     = (const float*)d_in[4];
    const float* wv     = (const float*)d_in[5];
    const float* wo     = (const float*)d_in[6];
    const float* w1     = (const float*)d_in[7];
    const float* w2     = (const float*)d_in[8];
    const float* w3     = (const float*)d_in[9];
    const float* anw    = (const float*)d_in[10];
    const float* fnw    = (const float*)d_in[11];
    float* out = (float*)d_out;

    static cudaStream_t s2 = nullptr;
    static cudaEvent_t evF = nullptr, evA = nullptr, evB = nullptr;
    if (s2 == nullptr) {
        cudaStreamCreateWithFlags(&s2, cudaStreamNonBlocking);
        cudaEventCreateWithFlags(&evF, cudaEventDisableTiming);
        cudaEventCreateWithFlags(&evA, cudaEventDisableTiming);
        cudaEventCreateWithFlags(&evB, cudaEventDisableTiming);
    }

    cudaFuncSetAttribute(hgemm, cudaFuncAttributeMaxDynamicSharedMemorySize, GEMM_SMEM);
    cudaFuncSetAttribute(flash_attn, cudaFuncAttributeMaxDynamicSharedMemorySize, FA_SMEM);

    h16 *xb, *wqkvT, *woT, *w13T, *w2T, *qb, *kb, *vb, *attnb, *yb, *gb;
    float *h;
    cudaGetSymbolAddress((void**)&xb,    g_xb);
    cudaGetSymbolAddress((void**)&wqkvT, g_wqkvT);
    cudaGetSymbolAddress((void**)&woT,   g_woT);
    cudaGetSymbolAddress((void**)&w13T,  g_w13T);
    cudaGetSymbolAddress((void**)&w2T,   g_w2T);
    cudaGetSymbolAddress((void**)&qb,    g_qb);
    cudaGetSymbolAddress((void**)&kb,    g_kb);
    cudaGetSymbolAddress((void**)&vb,    g_vb);
    cudaGetSymbolAddress((void**)&attnb, g_attnb);
    cudaGetSymbolAddress((void**)&h,     g_h);
    cudaGetSymbolAddress((void**)&yb,    g_yb);
    cudaGetSymbolAddress((void**)&gb,    g_gb);

    // ---- fork side stream for weight prep
    cudaEventRecord(evF, 0);
    cudaStreamWaitEvent(s2, evF, 0);

    { dim3 g(DD / 32, DD / 32);
      transpose_h16<<<g, 256, 0, s2>>>(wq, wqkvT,                          DD, DD, 1, 0);
      transpose_h16<<<g, 256, 0, s2>>>(wk, wqkvT + (long long)DD * DD,     DD, DD, 1, 0);
      transpose_h16<<<g, 256, 0, s2>>>(wv, wqkvT + (long long)2 * DD * DD, DD, DD, 1, 0); }
    cudaEventRecord(evA, s2);
    { dim3 g(DD / 32, DD / 32);
      transpose_h16<<<g, 256, 0, s2>>>(wo, woT, DD, DD, 1, 0); }
    { dim3 g(FFD / 32, DD / 32);
      transpose_h16<<<g, 256, 0, s2>>>(w1, w13T, DD, FFD, 2, 0);   // even rows
      transpose_h16<<<g, 256, 0, s2>>>(w3, w13T, DD, FFD, 2, 1); } // odd rows
    { dim3 g(DD / 32, FFD / 32);
      transpose_h16<<<g, 256, 0, s2>>>(w2, w2T, FFD, DD, 1, 0); }
    cudaEventRecord(evB, s2);

    // ---- main chain (default stream)
    // 1. x = rmsnorm(hidden) -> fp16
    rmsnorm_h16<<<MM, 256>>>(hidden, anw, xb);

    cudaStreamWaitEvent(0, evA, 0);
    // 2. qkv GEMM with fused rope epilogue -> qb (roped), kb (roped), vb
    gemm(xb, wqkvT, nullptr, nullptr, qb, kb, vb, fcos, fsin,
         MM, QKVN, DD, DD, DD, DD, 0, 1.0f, 3, 0);

    // 3. fused flash attention (V natural layout) -> attnb fp16
    { dim3 g(SS / 128, BBATCH * HH);
      flash_attn<<<g, 256, FA_SMEM>>>(qb, kb, vb, attnb); }

    cudaStreamWaitEvent(0, evB, 0);
    // 4. h = hidden + attn @ wo
    gemm(attnb, woT, hidden, h, nullptr, nullptr, nullptr, nullptr, nullptr,
         MM, DD, DD, DD, DD, DD, DD, 1.0f, 0, 0);

    // 5. y = rmsnorm(h) -> fp16
    rmsnorm_h16<<<MM, 256>>>(h, fnw, yb);

    // 6. g = silu(y@w1) * (y@w3) -> fp16 (fused epilogue, interleaved weights)
    gemm(yb, w13T, nullptr, nullptr, gb, nullptr, nullptr, nullptr, nullptr,
         MM, F13N, DD, DD, DD, FFD, 0, 1.0f, 2, 0);

    // 7. out = h + g @ w2
    gemm(gb, w2T, h, out, nullptr, nullptr, nullptr, nullptr, nullptr,
         MM, DD, FFD, FFD, FFD, DD, DD, 1.0f, 0, 0);
}